// round 1
// baseline (speedup 1.0000x reference)
#include <cuda_runtime.h>

// Problem constants
#define BB 4
#define SS 2048
#define DD 1024
#define MM (BB*SS)          // 8192 rows for QKV projection

// GEMM tiling
#define BM 128
#define BN 128
#define BK 16

// Scratch (allocation-free rule: __device__ globals)
__device__ float g_q[(size_t)MM * DD];
__device__ float g_k[(size_t)MM * DD];
__device__ float g_v[(size_t)MM * DD];
__device__ float g_sc[(size_t)BB * SS * SS];

// ---------------------------------------------------------------------------
// Shared GEMM body: C[row0.., col0..] += alpha * A * B^T (+bias)
// A: rows row0..row0+127, leading dim K (K-major)
// B: rows col0..col0+127, leading dim K (K-major)
// ---------------------------------------------------------------------------
__device__ __forceinline__ void gemm_nt_body(
    const float* __restrict__ A,
    const float* __restrict__ Bm,
    const float* __restrict__ bias,
    float* __restrict__ C, int ldC,
    int K, int row0, int col0, float alpha)
{
    __shared__ float As[BK][BM];
    __shared__ float Bs[BK][BN];

    const int tid  = threadIdx.x;
    const int lrow = tid >> 2;          // 0..63
    const int lcol = (tid & 3) << 2;    // 0,4,8,12
    const int tx   = tid & 15;
    const int ty   = tid >> 4;

    float acc[8][8];
#pragma unroll
    for (int i = 0; i < 8; i++)
#pragma unroll
        for (int j = 0; j < 8; j++) acc[i][j] = 0.f;

    for (int k0 = 0; k0 < K; k0 += BK) {
#pragma unroll
        for (int r = 0; r < 2; r++) {
            int m = lrow + r * 64;
            float4 a = *(const float4*)(A + (size_t)(row0 + m) * K + k0 + lcol);
            As[lcol + 0][m] = a.x; As[lcol + 1][m] = a.y;
            As[lcol + 2][m] = a.z; As[lcol + 3][m] = a.w;
            float4 b = *(const float4*)(Bm + (size_t)(col0 + m) * K + k0 + lcol);
            Bs[lcol + 0][m] = b.x; Bs[lcol + 1][m] = b.y;
            Bs[lcol + 2][m] = b.z; Bs[lcol + 3][m] = b.w;
        }
        __syncthreads();
#pragma unroll
        for (int kk = 0; kk < BK; kk++) {
            float af[8], bf[8];
            *(float4*)&af[0] = *(const float4*)&As[kk][ty * 8];
            *(float4*)&af[4] = *(const float4*)&As[kk][ty * 8 + 4];
            *(float4*)&bf[0] = *(const float4*)&Bs[kk][tx * 8];
            *(float4*)&bf[4] = *(const float4*)&Bs[kk][tx * 8 + 4];
#pragma unroll
            for (int i = 0; i < 8; i++)
#pragma unroll
                for (int j = 0; j < 8; j++)
                    acc[i][j] += af[i] * bf[j];
        }
        __syncthreads();
    }

#pragma unroll
    for (int i = 0; i < 8; i++) {
        int m = row0 + ty * 8 + i;
#pragma unroll
        for (int j = 0; j < 8; j += 4) {
            int n = col0 + tx * 8 + j;
            float4 v;
            v.x = alpha * acc[i][j + 0] + (bias ? bias[n + 0] : 0.f);
            v.y = alpha * acc[i][j + 1] + (bias ? bias[n + 1] : 0.f);
            v.z = alpha * acc[i][j + 2] + (bias ? bias[n + 2] : 0.f);
            v.w = alpha * acc[i][j + 3] + (bias ? bias[n + 3] : 0.f);
            *(float4*)(C + (size_t)m * ldC + n) = v;
        }
    }
}

// ---------------------------------------------------------------------------
// Kernel 1: QKV projections.  z selects {Wq,Wk,Wv}.
// q[m,e] = sum_d x[m,d]*W[e,d] + b[e]   (both operands K-major)
// ---------------------------------------------------------------------------
__global__ __launch_bounds__(256) void qkv_kernel(
    const float* __restrict__ x,
    const float* __restrict__ Wq, const float* __restrict__ bq,
    const float* __restrict__ Wk, const float* __restrict__ bk,
    const float* __restrict__ Wv, const float* __restrict__ bv)
{
    const float* W; const float* bias; float* C;
    int z = blockIdx.z;
    if (z == 0)      { W = Wq; bias = bq; C = g_q; }
    else if (z == 1) { W = Wk; bias = bk; C = g_k; }
    else             { W = Wv; bias = bv; C = g_v; }
    gemm_nt_body(x, W, bias, C, DD, DD,
                 blockIdx.y * BM, blockIdx.x * BN, 1.0f);
}

// ---------------------------------------------------------------------------
// Kernel 2: scores = (Q K^T) * 1/sqrt(D), per batch; upper-triangular
// 128x128 blocks skipped entirely (softmax never reads above the diagonal).
// ---------------------------------------------------------------------------
__global__ __launch_bounds__(256) void scores_kernel()
{
    int bx = blockIdx.x, by = blockIdx.y, z = blockIdx.z;
    if (bx > by) return;  // block fully above causal diagonal
    const float* q = g_q + (size_t)z * SS * DD;
    const float* k = g_k + (size_t)z * SS * DD;
    float* c = g_sc + (size_t)z * SS * SS;
    gemm_nt_body(q, k, nullptr, c, SS, DD,
                 by * BM, bx * BN, 0.03125f);  // 1/sqrt(1024)
}

// ---------------------------------------------------------------------------
// Kernel 3: causal row softmax in-place; zero-fill j > i so the PV GEMM can
// run dense tiles.
// ---------------------------------------------------------------------------
__global__ __launch_bounds__(256) void softmax_kernel()
{
    int row = blockIdx.x;          // 0..B*S-1
    int b = row >> 11;             // / 2048
    int i = row & (SS - 1);
    float* p = g_sc + (size_t)b * SS * SS + (size_t)i * SS;
    int len = i + 1;
    int tid = threadIdx.x;
    int lane = tid & 31, wid = tid >> 5;
    __shared__ float red[8];

    // ---- max ----
    float m = __int_as_float(0xff800000);  // -inf
    for (int j = tid; j < len; j += 256) m = fmaxf(m, p[j]);
#pragma unroll
    for (int o = 16; o; o >>= 1) m = fmaxf(m, __shfl_xor_sync(0xffffffffu, m, o));
    if (lane == 0) red[wid] = m;
    __syncthreads();
    if (tid == 0) {
        float mm = red[0];
#pragma unroll
        for (int w = 1; w < 8; w++) mm = fmaxf(mm, red[w]);
        red[0] = mm;
    }
    __syncthreads();
    m = red[0];
    __syncthreads();

    // ---- exp + sum ----
    float s = 0.f;
    for (int j = tid; j < len; j += 256) {
        float e = __expf(p[j] - m);
        p[j] = e;
        s += e;
    }
#pragma unroll
    for (int o = 16; o; o >>= 1) s += __shfl_xor_sync(0xffffffffu, s, o);
    if (lane == 0) red[wid] = s;
    __syncthreads();
    if (tid == 0) {
        float ss = 0.f;
#pragma unroll
        for (int w = 0; w < 8; w++) ss += red[w];
        red[0] = ss;
    }
    __syncthreads();
    float inv = 1.f / red[0];

    // ---- normalize + zero-fill upper triangle ----
    for (int j = tid; j < SS; j += 256) {
        if (j < len) p[j] *= inv;
        else         p[j] = 0.f;
    }
}

// ---------------------------------------------------------------------------
// Kernel 4: out = weights @ V  (A row-major [S,S], B row-major [S,D]).
// K loop capped at the diagonal of this block-row (weights zeroed above diag).
// ---------------------------------------------------------------------------
__global__ __launch_bounds__(256) void out_kernel(float* __restrict__ out)
{
    int z = blockIdx.z;
    const float* A  = g_sc + (size_t)z * SS * SS;   // [S,S]
    const float* Bm = g_v  + (size_t)z * SS * DD;   // [S,D]
    float* C = out + (size_t)z * SS * DD;

    int row0 = blockIdx.y * BM, col0 = blockIdx.x * BN;
    int kmax = min(SS, row0 + BM);   // multiple of BK

    __shared__ float As[BK][BM];
    __shared__ float Bs[BK][BN];

    const int tid  = threadIdx.x;
    const int lrow = tid >> 2;          // A loader: 0..63
    const int lcol = (tid & 3) << 2;
    const int brow = tid >> 5;          // B loader: 0..7
    const int bcol = (tid & 31) << 2;   // 0..124
    const int tx   = tid & 15;
    const int ty   = tid >> 4;

    float acc[8][8];
#pragma unroll
    for (int i = 0; i < 8; i++)
#pragma unroll
        for (int j = 0; j < 8; j++) acc[i][j] = 0.f;

    for (int k0 = 0; k0 < kmax; k0 += BK) {
#pragma unroll
        for (int r = 0; r < 2; r++) {
            int m = lrow + r * 64;
            float4 a = *(const float4*)(A + (size_t)(row0 + m) * SS + k0 + lcol);
            As[lcol + 0][m] = a.x; As[lcol + 1][m] = a.y;
            As[lcol + 2][m] = a.z; As[lcol + 3][m] = a.w;
        }
#pragma unroll
        for (int r = 0; r < 2; r++) {
            int kr = brow + r * 8;
            float4 b = *(const float4*)(Bm + (size_t)(k0 + kr) * DD + col0 + bcol);
            *(float4*)&Bs[kr][bcol] = b;
        }
        __syncthreads();
#pragma unroll
        for (int kk = 0; kk < BK; kk++) {
            float af[8], bf[8];
            *(float4*)&af[0] = *(const float4*)&As[kk][ty * 8];
            *(float4*)&af[4] = *(const float4*)&As[kk][ty * 8 + 4];
            *(float4*)&bf[0] = *(const float4*)&Bs[kk][tx * 8];
            *(float4*)&bf[4] = *(const float4*)&Bs[kk][tx * 8 + 4];
#pragma unroll
            for (int i = 0; i < 8; i++)
#pragma unroll
                for (int j = 0; j < 8; j++)
                    acc[i][j] += af[i] * bf[j];
        }
        __syncthreads();
    }

#pragma unroll
    for (int i = 0; i < 8; i++) {
        int m = row0 + ty * 8 + i;
#pragma unroll
        for (int j = 0; j < 8; j += 4) {
            int n = col0 + tx * 8 + j;
            float4 v;
            v.x = acc[i][j + 0]; v.y = acc[i][j + 1];
            v.z = acc[i][j + 2]; v.w = acc[i][j + 3];
            *(float4*)(C + (size_t)m * DD + n) = v;
        }
    }
}

// ---------------------------------------------------------------------------
extern "C" void kernel_launch(void* const* d_in, const int* in_sizes, int n_in,
                              void* d_out, int out_size)
{
    const float* x  = (const float*)d_in[0];
    const float* Wq = (const float*)d_in[1];
    const float* bq = (const float*)d_in[2];
    const float* Wk = (const float*)d_in[3];
    const float* bk = (const float*)d_in[4];
    const float* Wv = (const float*)d_in[5];
    const float* bv = (const float*)d_in[6];
    float* out = (float*)d_out;

    dim3 blk(256);
    qkv_kernel<<<dim3(DD / BN, MM / BM, 3), blk>>>(x, Wq, bq, Wk, bk, Wv, bv);
    scores_kernel<<<dim3(SS / BN, SS / BM, BB), blk>>>();
    softmax_kernel<<<BB * SS, blk>>>();
    out_kernel<<<dim3(DD / BN, SS / BM, BB), blk>>>(out);
}

// round 2
// speedup vs baseline: 1.9058x; 1.9058x over previous
#include <cuda_runtime.h>
#include <cuda_bf16.h>
#include <cstdint>

// Problem constants
#define BB 4
#define SS 2048
#define DD 1024
#define MM (BB*SS)       // 8192
#define K3 (3*DD)        // 3072  (split-tripled K for projections/scores)
#define S3 (3*SS)        // 6144  (split-tripled K for PV)

// GEMM tiling
#define TM 128
#define TN 128
#define TK 32
#define AST 40           // TK + 8 pad: row stride 20 words -> conflict-free

// ---------------------------------------------------------------------------
// Scratch (__device__ globals: allocation-free rule)
// Split layouts:  A-type row = [hi | lo | hi], B-type row = [hi | hi | lo]
// so a plain bf16 GEMM over tripled K computes hi*hi + lo*hi + hi*lo.
// ---------------------------------------------------------------------------
__device__ __nv_bfloat16 g_xs[(size_t)MM * K3];        // x split, A-type
__device__ __nv_bfloat16 g_wq[(size_t)DD * K3];        // W splits, B-type
__device__ __nv_bfloat16 g_wk[(size_t)DD * K3];
__device__ __nv_bfloat16 g_wv[(size_t)DD * K3];
__device__ __nv_bfloat16 g_qs[(size_t)MM * K3];        // Q split, A-type
__device__ __nv_bfloat16 g_ks[(size_t)MM * K3];        // K split, B-type
__device__ __nv_bfloat16 g_vt[(size_t)BB * DD * S3];   // V^T split, B-type over seq
__device__ float         g_sc[(size_t)BB * SS * SS];   // scores fp32
__device__ __nv_bfloat16 g_ps[(size_t)BB * SS * S3];   // softmax weights, A-type

__device__ __forceinline__ void split2(float v, __nv_bfloat16& h, __nv_bfloat16& l) {
    h = __float2bfloat16(v);
    l = __float2bfloat16(v - __bfloat162float(h));
}

// ---------------------------------------------------------------------------
// Split input kernels
// ---------------------------------------------------------------------------
__global__ __launch_bounds__(256) void split_x_kernel(const float* __restrict__ x)
{
    size_t idx = (size_t)blockIdx.x * 256 + threadIdx.x;   // < MM*DD
    size_t m = idx >> 10, d = idx & (DD - 1);
    __nv_bfloat16 h, l;
    split2(x[idx], h, l);
    __nv_bfloat16* r = g_xs + m * K3;
    r[d] = h; r[DD + d] = l; r[2 * DD + d] = h;            // A-type
}

__global__ __launch_bounds__(256) void split_w_kernel(
    const float* __restrict__ Wq, const float* __restrict__ Wk,
    const float* __restrict__ Wv)
{
    int z = blockIdx.z;
    size_t idx = (size_t)blockIdx.x * 256 + threadIdx.x;   // < DD*DD
    const float* W = (z == 0) ? Wq : (z == 1) ? Wk : Wv;
    __nv_bfloat16* O = (z == 0) ? g_wq : (z == 1) ? g_wk : g_wv;
    size_t e = idx >> 10, d = idx & (DD - 1);
    __nv_bfloat16 h, l;
    split2(W[idx], h, l);
    __nv_bfloat16* r = O + e * K3;
    r[d] = h; r[DD + d] = h; r[2 * DD + d] = l;            // B-type
}

// ---------------------------------------------------------------------------
// GEMM core: C[128x128] = A[row0..][.] * B[col0..][.]^T over bf16, K-major
// operands, mma.sync m16n8k16, cp.async double-buffered.
// ---------------------------------------------------------------------------
struct KLin {
    __device__ __forceinline__ int operator()(int t) const { return t * TK; }
};
struct KSeg {
    int tps;  // tiles per segment
    __device__ __forceinline__ int operator()(int t) const {
        int s = t / tps; return s * SS + (t - s * tps) * TK;
    }
};

template <typename KF>
__device__ __forceinline__ void gemm_core(
    const __nv_bfloat16* __restrict__ A, int row0, size_t lda,
    const __nv_bfloat16* __restrict__ B, int col0, size_t ldb,
    int ntiles, KF koff, float acc[4][4][4])
{
    __shared__ __align__(16) __nv_bfloat16 As[2][TM][AST];
    __shared__ __align__(16) __nv_bfloat16 Bs[2][TN][AST];

    const int tid  = threadIdx.x;
    const int lrow = tid >> 2;            // 0..63
    const int lcol = (tid & 3) << 3;      // 0,8,16,24
    const int lane = tid & 31, warp = tid >> 5;
    const int wm = (warp & 1) << 6;       // 0/64
    const int wn = (warp >> 1) << 5;      // 0/32/64/96
    const int g = lane >> 2, tig = lane & 3;

    auto LD = [&](int t, int buf) {
        int ko = koff(t);
#pragma unroll
        for (int r = 0; r < 2; r++) {
            int m = lrow + (r << 6);
            const void* sa = (const void*)(A + (size_t)(row0 + m) * lda + ko + lcol);
            uint32_t da = (uint32_t)__cvta_generic_to_shared(&As[buf][m][lcol]);
            asm volatile("cp.async.cg.shared.global [%0], [%1], 16;\n" :: "r"(da), "l"(sa));
            const void* sb = (const void*)(B + (size_t)(col0 + m) * ldb + ko + lcol);
            uint32_t db = (uint32_t)__cvta_generic_to_shared(&Bs[buf][m][lcol]);
            asm volatile("cp.async.cg.shared.global [%0], [%1], 16;\n" :: "r"(db), "l"(sb));
        }
        asm volatile("cp.async.commit_group;\n" ::: "memory");
    };

    LD(0, 0);
    for (int t = 0; t < ntiles; t++) {
        int buf = t & 1;
        if (t + 1 < ntiles) {
            LD(t + 1, buf ^ 1);
            asm volatile("cp.async.wait_group 1;\n" ::: "memory");
        } else {
            asm volatile("cp.async.wait_group 0;\n" ::: "memory");
        }
        __syncthreads();

#pragma unroll
        for (int kk = 0; kk < 2; kk++) {
            const int cw = (kk << 3) + tig;   // 32-bit word index within row
            uint32_t a[4][4], bfr[4][2];
#pragma unroll
            for (int mi = 0; mi < 4; mi++) {
                const uint32_t* r0 = (const uint32_t*)As[buf][wm + (mi << 4) + g];
                const uint32_t* r1 = (const uint32_t*)As[buf][wm + (mi << 4) + g + 8];
                a[mi][0] = r0[cw];     a[mi][1] = r1[cw];
                a[mi][2] = r0[cw + 4]; a[mi][3] = r1[cw + 4];
            }
#pragma unroll
            for (int ni = 0; ni < 4; ni++) {
                const uint32_t* rb = (const uint32_t*)Bs[buf][wn + (ni << 3) + g];
                bfr[ni][0] = rb[cw]; bfr[ni][1] = rb[cw + 4];
            }
#pragma unroll
            for (int mi = 0; mi < 4; mi++)
#pragma unroll
                for (int ni = 0; ni < 4; ni++) {
                    float* c = acc[mi][ni];
                    asm volatile(
                        "mma.sync.aligned.m16n8k16.row.col.f32.bf16.bf16.f32 "
                        "{%0,%1,%2,%3}, {%4,%5,%6,%7}, {%8,%9}, {%0,%1,%2,%3};\n"
                        : "+f"(c[0]), "+f"(c[1]), "+f"(c[2]), "+f"(c[3])
                        : "r"(a[mi][0]), "r"(a[mi][1]), "r"(a[mi][2]), "r"(a[mi][3]),
                          "r"(bfr[ni][0]), "r"(bfr[ni][1]));
                }
        }
        __syncthreads();
    }
}

// ---------------------------------------------------------------------------
// Kernel: QKV projections (z = 0/1/2 -> Q/K/V), epilogue writes bf16 splits.
// ---------------------------------------------------------------------------
__global__ __launch_bounds__(256, 2) void proj_kernel(
    const float* __restrict__ bq, const float* __restrict__ bk,
    const float* __restrict__ bv)
{
    const int z = blockIdx.z;
    const __nv_bfloat16* W = (z == 0) ? g_wq : (z == 1) ? g_wk : g_wv;
    const float* bias      = (z == 0) ? bq   : (z == 1) ? bk   : bv;
    const int row0 = blockIdx.y * TM, col0 = blockIdx.x * TN;

    float acc[4][4][4];
#pragma unroll
    for (int i = 0; i < 4; i++)
#pragma unroll
        for (int j = 0; j < 4; j++)
#pragma unroll
            for (int q = 0; q < 4; q++) acc[i][j][q] = 0.f;

    gemm_core(g_xs, row0, K3, W, col0, K3, K3 / TK, KLin{}, acc);

    const int lane = threadIdx.x & 31, warp = threadIdx.x >> 5;
    const int wm = (warp & 1) << 6, wn = (warp >> 1) << 5;
    const int g = lane >> 2, tig = lane & 3;

#pragma unroll
    for (int mi = 0; mi < 4; mi++)
#pragma unroll
        for (int ni = 0; ni < 4; ni++) {
            const int n = col0 + wn + (ni << 3) + (tig << 1);
            const float b0 = bias[n], b1 = bias[n + 1];
#pragma unroll
            for (int rr = 0; rr < 2; rr++) {
                const int m = row0 + wm + (mi << 4) + g + rr * 8;
                float v0 = acc[mi][ni][rr * 2 + 0] + b0;
                float v1 = acc[mi][ni][rr * 2 + 1] + b1;
                __nv_bfloat16 h0, l0, h1, l1;
                split2(v0, h0, l0); split2(v1, h1, l1);
                if (z == 0) {          // Q: A-type [hi|lo|hi]
                    __nv_bfloat16* r = g_qs + (size_t)m * K3 + n;
                    __nv_bfloat162 th; th.x = h0; th.y = h1;
                    __nv_bfloat162 tl; tl.x = l0; tl.y = l1;
                    *(__nv_bfloat162*)(r)          = th;
                    *(__nv_bfloat162*)(r + DD)     = tl;
                    *(__nv_bfloat162*)(r + 2 * DD) = th;
                } else if (z == 1) {   // K: B-type [hi|hi|lo]
                    __nv_bfloat16* r = g_ks + (size_t)m * K3 + n;
                    __nv_bfloat162 th; th.x = h0; th.y = h1;
                    __nv_bfloat162 tl; tl.x = l0; tl.y = l1;
                    *(__nv_bfloat162*)(r)          = th;
                    *(__nv_bfloat162*)(r + DD)     = th;
                    *(__nv_bfloat162*)(r + 2 * DD) = tl;
                } else {               // V: transposed into g_vt[b][d][3S], B-type
                    const int b = m >> 11, s = m & (SS - 1);
                    __nv_bfloat16* r0 = g_vt + ((size_t)b * DD + n) * S3 + s;
                    r0[0] = h0; r0[SS] = h0; r0[2 * SS] = l0;
                    __nv_bfloat16* r1 = g_vt + ((size_t)b * DD + n + 1) * S3 + s;
                    r1[0] = h1; r1[SS] = h1; r1[2 * SS] = l1;
                }
            }
        }
}

// ---------------------------------------------------------------------------
// Kernel: scores = Q K^T / sqrt(D); causal upper blocks skipped entirely.
// ---------------------------------------------------------------------------
__global__ __launch_bounds__(256, 2) void scores_kernel()
{
    const int bx = blockIdx.x, by = blockIdx.y, b = blockIdx.z;
    if (bx > by) return;
    const __nv_bfloat16* A  = g_qs + (size_t)b * SS * K3;
    const __nv_bfloat16* Bp = g_ks + (size_t)b * SS * K3;
    const int row0 = by * TM, col0 = bx * TN;

    float acc[4][4][4];
#pragma unroll
    for (int i = 0; i < 4; i++)
#pragma unroll
        for (int j = 0; j < 4; j++)
#pragma unroll
            for (int q = 0; q < 4; q++) acc[i][j][q] = 0.f;

    gemm_core(A, row0, K3, Bp, col0, K3, K3 / TK, KLin{}, acc);

    float* C = g_sc + (size_t)b * SS * SS;
    const int lane = threadIdx.x & 31, warp = threadIdx.x >> 5;
    const int wm = (warp & 1) << 6, wn = (warp >> 1) << 5;
    const int g = lane >> 2, tig = lane & 3;

#pragma unroll
    for (int mi = 0; mi < 4; mi++)
#pragma unroll
        for (int ni = 0; ni < 4; ni++) {
            const int n = col0 + wn + (ni << 3) + (tig << 1);
#pragma unroll
            for (int rr = 0; rr < 2; rr++) {
                const int m = row0 + wm + (mi << 4) + g + rr * 8;
                float2 v;
                v.x = acc[mi][ni][rr * 2 + 0] * 0.03125f;
                v.y = acc[mi][ni][rr * 2 + 1] * 0.03125f;
                *(float2*)(C + (size_t)m * SS + n) = v;
            }
        }
}

// ---------------------------------------------------------------------------
// Kernel: causal row softmax; writes split weights (A-type) with zero fill.
// ---------------------------------------------------------------------------
__global__ __launch_bounds__(256) void softmax_kernel()
{
    const int row = blockIdx.x;            // 0..B*S-1
    const int b = row >> 11;
    const int i = row & (SS - 1);
    const float* p = g_sc + (size_t)b * SS * SS + (size_t)i * SS;
    __nv_bfloat16* o = g_ps + (size_t)b * SS * S3 + (size_t)i * S3;
    const int len = i + 1;
    const int tid = threadIdx.x;
    const int lane = tid & 31, wid = tid >> 5;
    __shared__ float red[8];

    // ---- max ----
    float m = __int_as_float(0xff800000);
    float xv[8];
#pragma unroll
    for (int jj = 0; jj < 8; jj++) {
        int j = tid + jj * 256;
        xv[jj] = (j < len) ? p[j] : __int_as_float(0xff800000);
        m = fmaxf(m, xv[jj]);
    }
#pragma unroll
    for (int off = 16; off; off >>= 1) m = fmaxf(m, __shfl_xor_sync(0xffffffffu, m, off));
    if (lane == 0) red[wid] = m;
    __syncthreads();
    if (tid == 0) {
        float mm = red[0];
#pragma unroll
        for (int w = 1; w < 8; w++) mm = fmaxf(mm, red[w]);
        red[0] = mm;
    }
    __syncthreads();
    m = red[0];
    __syncthreads();

    // ---- exp + sum ----
    float s = 0.f;
    float ev[8];
#pragma unroll
    for (int jj = 0; jj < 8; jj++) {
        int j = tid + jj * 256;
        ev[jj] = (j < len) ? __expf(xv[jj] - m) : 0.f;
        s += ev[jj];
    }
#pragma unroll
    for (int off = 16; off; off >>= 1) s += __shfl_xor_sync(0xffffffffu, s, off);
    if (lane == 0) red[wid] = s;
    __syncthreads();
    if (tid == 0) {
        float ss = 0.f;
#pragma unroll
        for (int w = 0; w < 8; w++) ss += red[w];
        red[0] = ss;
    }
    __syncthreads();
    const float inv = 1.f / red[0];

    // ---- write A-type split [hi | lo | hi], zero above diagonal ----
#pragma unroll
    for (int jj = 0; jj < 8; jj++) {
        int j = tid + jj * 256;
        float w = ev[jj] * inv;            // 0 for j > i
        __nv_bfloat16 h, l;
        split2(w, h, l);
        o[j] = h; o[SS + j] = l; o[2 * SS + j] = h;
    }
}

// ---------------------------------------------------------------------------
// Kernel: out = P V ; K loop runs 3 causal-capped segments (hi, lo, hi parts).
// ---------------------------------------------------------------------------
__global__ __launch_bounds__(256, 2) void pv_kernel(float* __restrict__ out)
{
    const int bx = blockIdx.x, by = blockIdx.y, b = blockIdx.z;
    const __nv_bfloat16* A  = g_ps + (size_t)b * SS * S3;
    const __nv_bfloat16* Bp = g_vt + (size_t)b * DD * S3;
    const int row0 = by * TM, col0 = bx * TN;
    const int tps = (row0 + TM) / TK;      // causal cap per segment

    float acc[4][4][4];
#pragma unroll
    for (int i = 0; i < 4; i++)
#pragma unroll
        for (int j = 0; j < 4; j++)
#pragma unroll
            for (int q = 0; q < 4; q++) acc[i][j][q] = 0.f;

    gemm_core(A, row0, S3, Bp, col0, S3, 3 * tps, KSeg{tps}, acc);

    float* C = out + (size_t)b * SS * DD;
    const int lane = threadIdx.x & 31, warp = threadIdx.x >> 5;
    const int wm = (warp & 1) << 6, wn = (warp >> 1) << 5;
    const int g = lane >> 2, tig = lane & 3;

#pragma unroll
    for (int mi = 0; mi < 4; mi++)
#pragma unroll
        for (int ni = 0; ni < 4; ni++) {
            const int n = col0 + wn + (ni << 3) + (tig << 1);
#pragma unroll
            for (int rr = 0; rr < 2; rr++) {
                const int m = row0 + wm + (mi << 4) + g + rr * 8;
                float2 v;
                v.x = acc[mi][ni][rr * 2 + 0];
                v.y = acc[mi][ni][rr * 2 + 1];
                *(float2*)(C + (size_t)m * DD + n) = v;
            }
        }
}

// ---------------------------------------------------------------------------
extern "C" void kernel_launch(void* const* d_in, const int* in_sizes, int n_in,
                              void* d_out, int out_size)
{
    const float* x  = (const float*)d_in[0];
    const float* Wq = (const float*)d_in[1];
    const float* bq = (const float*)d_in[2];
    const float* Wk = (const float*)d_in[3];
    const float* bk = (const float*)d_in[4];
    const float* Wv = (const float*)d_in[5];
    const float* bv = (const float*)d_in[6];
    float* out = (float*)d_out;

    split_x_kernel<<<(MM * DD) / 256, 256>>>(x);
    split_w_kernel<<<dim3((DD * DD) / 256, 1, 3), 256>>>(Wq, Wk, Wv);
    proj_kernel<<<dim3(DD / TN, MM / TM, 3), 256>>>(bq, bk, bv);
    scores_kernel<<<dim3(SS / TN, SS / TM, BB), 256>>>();
    softmax_kernel<<<BB * SS, 256>>>();
    pv_kernel<<<dim3(DD / TN, SS / TM, BB), 256>>>(out);
}

// round 3
// speedup vs baseline: 2.3323x; 1.2237x over previous
#include <cuda_runtime.h>
#include <cuda_bf16.h>
#include <cstdint>

// Problem constants
#define BB 4
#define SS 2048
#define DD 1024
#define MM (BB*SS)       // 8192
#define K3 (3*DD)        // 3072  (split-tripled K for projections/scores)
#define S3 (3*SS)        // 6144  (split-tripled K for PV)

// GEMM tiling
#define TM 128
#define TN 128
#define TK 32
#define AST 40           // TK + 8 pad: 80B row stride = 5*16B (ldmatrix-aligned,
                         // start banks 20*i mod 32 -> conflict-free)

// ---------------------------------------------------------------------------
// Scratch (__device__ globals: allocation-free rule)
// Split layouts:  A-type row = [hi | lo | hi], B-type row = [hi | hi | lo]
// so a plain bf16 GEMM over tripled K computes hi*hi + lo*hi + hi*lo.
// ---------------------------------------------------------------------------
__device__ __nv_bfloat16 g_xs[(size_t)MM * K3];        // x split, A-type
__device__ __nv_bfloat16 g_wq[(size_t)DD * K3];        // W splits, B-type
__device__ __nv_bfloat16 g_wk[(size_t)DD * K3];
__device__ __nv_bfloat16 g_wv[(size_t)DD * K3];
__device__ __nv_bfloat16 g_qs[(size_t)MM * K3];        // Q split, A-type
__device__ __nv_bfloat16 g_ks[(size_t)MM * K3];        // K split, B-type
__device__ __nv_bfloat16 g_vt[(size_t)BB * DD * S3];   // V^T split, B-type over seq
__device__ float         g_sc[(size_t)BB * SS * SS];   // scores fp32
__device__ __nv_bfloat16 g_ps[(size_t)BB * SS * S3];   // softmax weights, A-type

__device__ __forceinline__ void split2(float v, __nv_bfloat16& h, __nv_bfloat16& l) {
    h = __float2bfloat16(v);
    l = __float2bfloat16(v - __bfloat162float(h));
}

// ---------------------------------------------------------------------------
// Split input kernels
// ---------------------------------------------------------------------------
__global__ __launch_bounds__(256) void split_x_kernel(const float* __restrict__ x)
{
    size_t idx = (size_t)blockIdx.x * 256 + threadIdx.x;   // < MM*DD
    size_t m = idx >> 10, d = idx & (DD - 1);
    __nv_bfloat16 h, l;
    split2(x[idx], h, l);
    __nv_bfloat16* r = g_xs + m * K3;
    r[d] = h; r[DD + d] = l; r[2 * DD + d] = h;            // A-type
}

__global__ __launch_bounds__(256) void split_w_kernel(
    const float* __restrict__ Wq, const float* __restrict__ Wk,
    const float* __restrict__ Wv)
{
    int z = blockIdx.z;
    size_t idx = (size_t)blockIdx.x * 256 + threadIdx.x;   // < DD*DD
    const float* W = (z == 0) ? Wq : (z == 1) ? Wk : Wv;
    __nv_bfloat16* O = (z == 0) ? g_wq : (z == 1) ? g_wk : g_wv;
    size_t e = idx >> 10, d = idx & (DD - 1);
    __nv_bfloat16 h, l;
    split2(W[idx], h, l);
    __nv_bfloat16* r = O + e * K3;
    r[d] = h; r[DD + d] = h; r[2 * DD + d] = l;            // B-type
}

// ---------------------------------------------------------------------------
// GEMM core: C[128x128] = A[row0..][.] * B[col0..][.]^T over bf16, K-major
// operands. ldmatrix.x4 fragment loads + mma.sync m16n8k16, cp.async
// double-buffered.
// ---------------------------------------------------------------------------
struct KLin {
    __device__ __forceinline__ int operator()(int t) const { return t * TK; }
};
struct KSeg {
    int tps;  // tiles per segment
    __device__ __forceinline__ int operator()(int t) const {
        int s = t / tps; return s * SS + (t - s * tps) * TK;
    }
};

#define LDSM_X4(r0, r1, r2, r3, addr) \
    asm volatile("ldmatrix.sync.aligned.m8n8.x4.shared.b16 {%0,%1,%2,%3}, [%4];" \
                 : "=r"(r0), "=r"(r1), "=r"(r2), "=r"(r3) : "r"(addr))

template <typename KF>
__device__ __forceinline__ void gemm_core(
    const __nv_bfloat16* __restrict__ A, int row0, size_t lda,
    const __nv_bfloat16* __restrict__ B, int col0, size_t ldb,
    int ntiles, KF koff, float acc[4][4][4])
{
    __shared__ __align__(16) __nv_bfloat16 As[2][TM][AST];
    __shared__ __align__(16) __nv_bfloat16 Bs[2][TN][AST];

    const int tid  = threadIdx.x;
    const int lrow = tid >> 2;            // 0..63
    const int lcol = (tid & 3) << 3;      // 0,8,16,24
    const int lane = tid & 31, warp = tid >> 5;
    const int wm = (warp & 1) << 6;       // 0/64
    const int wn = (warp >> 1) << 5;      // 0/32/64/96
    const int lr  = lane & 7;
    const int seg = lane >> 3;            // 0..3

    // ldmatrix lane-address bases (bytes), per double-buffer:
    //   A x4: m0 lanes0-7  rows m0..m0+7  @k-lo | m1 lanes8-15 rows m0+8..15 @k-lo
    //         m2 lanes16-23 rows m0..m0+7 @k-hi | m3 lanes24-31 rows +8      @k-hi
    //   B x4: m0 rows n0..n0+7 @k-lo | m1 same rows @k-hi | m2 rows +8 @k-lo | m3 +8 @k-hi
    uint32_t aAddr[2], bAddr[2];
#pragma unroll
    for (int bf = 0; bf < 2; bf++) {
        aAddr[bf] = (uint32_t)__cvta_generic_to_shared(
            &As[bf][wm + ((seg & 1) << 3) + lr][(seg >> 1) << 3]);
        bAddr[bf] = (uint32_t)__cvta_generic_to_shared(
            &Bs[bf][wn + ((seg >> 1) << 3) + lr][(seg & 1) << 3]);
    }

    auto LD = [&](int t, int buf) {
        int ko = koff(t);
#pragma unroll
        for (int r = 0; r < 2; r++) {
            int m = lrow + (r << 6);
            const void* sa = (const void*)(A + (size_t)(row0 + m) * lda + ko + lcol);
            uint32_t da = (uint32_t)__cvta_generic_to_shared(&As[buf][m][lcol]);
            asm volatile("cp.async.cg.shared.global [%0], [%1], 16;\n" :: "r"(da), "l"(sa));
            const void* sb = (const void*)(B + (size_t)(col0 + m) * ldb + ko + lcol);
            uint32_t db = (uint32_t)__cvta_generic_to_shared(&Bs[buf][m][lcol]);
            asm volatile("cp.async.cg.shared.global [%0], [%1], 16;\n" :: "r"(db), "l"(sb));
        }
        asm volatile("cp.async.commit_group;\n" ::: "memory");
    };

    LD(0, 0);
    for (int t = 0; t < ntiles; t++) {
        int buf = t & 1;
        if (t + 1 < ntiles) {
            LD(t + 1, buf ^ 1);
            asm volatile("cp.async.wait_group 1;\n" ::: "memory");
        } else {
            asm volatile("cp.async.wait_group 0;\n" ::: "memory");
        }
        __syncthreads();

#pragma unroll
        for (int kk = 0; kk < 2; kk++) {
            const uint32_t akk = aAddr[buf] + kk * 32;   // 16 bf16 = 32B per k-step
            const uint32_t bkk = bAddr[buf] + kk * 32;
            uint32_t a[4][4], bfr[2][4];
#pragma unroll
            for (int mi = 0; mi < 4; mi++)
                LDSM_X4(a[mi][0], a[mi][1], a[mi][2], a[mi][3],
                        akk + mi * (16 * AST * 2));
#pragma unroll
            for (int n2 = 0; n2 < 2; n2++)
                LDSM_X4(bfr[n2][0], bfr[n2][1], bfr[n2][2], bfr[n2][3],
                        bkk + n2 * (16 * AST * 2));
#pragma unroll
            for (int mi = 0; mi < 4; mi++)
#pragma unroll
                for (int ni = 0; ni < 4; ni++) {
                    float* c = acc[mi][ni];
                    const uint32_t b0 = bfr[ni >> 1][(ni & 1) << 1];
                    const uint32_t b1 = bfr[ni >> 1][((ni & 1) << 1) + 1];
                    asm volatile(
                        "mma.sync.aligned.m16n8k16.row.col.f32.bf16.bf16.f32 "
                        "{%0,%1,%2,%3}, {%4,%5,%6,%7}, {%8,%9}, {%0,%1,%2,%3};\n"
                        : "+f"(c[0]), "+f"(c[1]), "+f"(c[2]), "+f"(c[3])
                        : "r"(a[mi][0]), "r"(a[mi][1]), "r"(a[mi][2]), "r"(a[mi][3]),
                          "r"(b0), "r"(b1));
                }
        }
        __syncthreads();
    }
}

// ---------------------------------------------------------------------------
// Kernel: QKV projections (z = 0/1/2 -> Q/K/V), epilogue writes bf16 splits.
// ---------------------------------------------------------------------------
__global__ __launch_bounds__(256, 2) void proj_kernel(
    const float* __restrict__ bq, const float* __restrict__ bk,
    const float* __restrict__ bv)
{
    const int z = blockIdx.z;
    const __nv_bfloat16* W = (z == 0) ? g_wq : (z == 1) ? g_wk : g_wv;
    const float* bias      = (z == 0) ? bq   : (z == 1) ? bk   : bv;
    const int row0 = blockIdx.y * TM, col0 = blockIdx.x * TN;

    float acc[4][4][4];
#pragma unroll
    for (int i = 0; i < 4; i++)
#pragma unroll
        for (int j = 0; j < 4; j++)
#pragma unroll
            for (int q = 0; q < 4; q++) acc[i][j][q] = 0.f;

    gemm_core(g_xs, row0, K3, W, col0, K3, K3 / TK, KLin{}, acc);

    const int lane = threadIdx.x & 31, warp = threadIdx.x >> 5;
    const int wm = (warp & 1) << 6, wn = (warp >> 1) << 5;
    const int g = lane >> 2, tig = lane & 3;

#pragma unroll
    for (int mi = 0; mi < 4; mi++)
#pragma unroll
        for (int ni = 0; ni < 4; ni++) {
            const int n = col0 + wn + (ni << 3) + (tig << 1);
            const float b0 = bias[n], b1 = bias[n + 1];
#pragma unroll
            for (int rr = 0; rr < 2; rr++) {
                const int m = row0 + wm + (mi << 4) + g + rr * 8;
                float v0 = acc[mi][ni][rr * 2 + 0] + b0;
                float v1 = acc[mi][ni][rr * 2 + 1] + b1;
                __nv_bfloat16 h0, l0, h1, l1;
                split2(v0, h0, l0); split2(v1, h1, l1);
                if (z == 0) {          // Q: A-type [hi|lo|hi]
                    __nv_bfloat16* r = g_qs + (size_t)m * K3 + n;
                    __nv_bfloat162 th; th.x = h0; th.y = h1;
                    __nv_bfloat162 tl; tl.x = l0; tl.y = l1;
                    *(__nv_bfloat162*)(r)          = th;
                    *(__nv_bfloat162*)(r + DD)     = tl;
                    *(__nv_bfloat162*)(r + 2 * DD) = th;
                } else if (z == 1) {   // K: B-type [hi|hi|lo]
                    __nv_bfloat16* r = g_ks + (size_t)m * K3 + n;
                    __nv_bfloat162 th; th.x = h0; th.y = h1;
                    __nv_bfloat162 tl; tl.x = l0; tl.y = l1;
                    *(__nv_bfloat162*)(r)          = th;
                    *(__nv_bfloat162*)(r + DD)     = th;
                    *(__nv_bfloat162*)(r + 2 * DD) = tl;
                } else {               // V: transposed into g_vt[b][d][3S], B-type
                    const int b = m >> 11, s = m & (SS - 1);
                    __nv_bfloat16* r0 = g_vt + ((size_t)b * DD + n) * S3 + s;
                    r0[0] = h0; r0[SS] = h0; r0[2 * SS] = l0;
                    __nv_bfloat16* r1 = g_vt + ((size_t)b * DD + n + 1) * S3 + s;
                    r1[0] = h1; r1[SS] = h1; r1[2 * SS] = l1;
                }
            }
        }
}

// ---------------------------------------------------------------------------
// Kernel: scores = Q K^T / sqrt(D); causal upper blocks skipped entirely.
// ---------------------------------------------------------------------------
__global__ __launch_bounds__(256, 2) void scores_kernel()
{
    const int bx = blockIdx.x, by = blockIdx.y, b = blockIdx.z;
    if (bx > by) return;
    const __nv_bfloat16* A  = g_qs + (size_t)b * SS * K3;
    const __nv_bfloat16* Bp = g_ks + (size_t)b * SS * K3;
    const int row0 = by * TM, col0 = bx * TN;

    float acc[4][4][4];
#pragma unroll
    for (int i = 0; i < 4; i++)
#pragma unroll
        for (int j = 0; j < 4; j++)
#pragma unroll
            for (int q = 0; q < 4; q++) acc[i][j][q] = 0.f;

    gemm_core(A, row0, K3, Bp, col0, K3, K3 / TK, KLin{}, acc);

    float* C = g_sc + (size_t)b * SS * SS;
    const int lane = threadIdx.x & 31, warp = threadIdx.x >> 5;
    const int wm = (warp & 1) << 6, wn = (warp >> 1) << 5;
    const int g = lane >> 2, tig = lane & 3;

#pragma unroll
    for (int mi = 0; mi < 4; mi++)
#pragma unroll
        for (int ni = 0; ni < 4; ni++) {
            const int n = col0 + wn + (ni << 3) + (tig << 1);
#pragma unroll
            for (int rr = 0; rr < 2; rr++) {
                const int m = row0 + wm + (mi << 4) + g + rr * 8;
                float2 v;
                v.x = acc[mi][ni][rr * 2 + 0] * 0.03125f;
                v.y = acc[mi][ni][rr * 2 + 1] * 0.03125f;
                *(float2*)(C + (size_t)m * SS + n) = v;
            }
        }
}

// ---------------------------------------------------------------------------
// Kernel: causal row softmax; writes split weights (A-type) with zero fill.
// ---------------------------------------------------------------------------
__global__ __launch_bounds__(256) void softmax_kernel()
{
    const int row = blockIdx.x;            // 0..B*S-1
    const int b = row >> 11;
    const int i = row & (SS - 1);
    const float* p = g_sc + (size_t)b * SS * SS + (size_t)i * SS;
    __nv_bfloat16* o = g_ps + (size_t)b * SS * S3 + (size_t)i * S3;
    const int len = i + 1;
    const int tid = threadIdx.x;
    const int lane = tid & 31, wid = tid >> 5;
    __shared__ float red[8];

    // ---- max ----
    float m = __int_as_float(0xff800000);
    float xv[8];
#pragma unroll
    for (int jj = 0; jj < 8; jj++) {
        int j = tid + jj * 256;
        xv[jj] = (j < len) ? p[j] : __int_as_float(0xff800000);
        m = fmaxf(m, xv[jj]);
    }
#pragma unroll
    for (int off = 16; off; off >>= 1) m = fmaxf(m, __shfl_xor_sync(0xffffffffu, m, off));
    if (lane == 0) red[wid] = m;
    __syncthreads();
    if (tid == 0) {
        float mm = red[0];
#pragma unroll
        for (int w = 1; w < 8; w++) mm = fmaxf(mm, red[w]);
        red[0] = mm;
    }
    __syncthreads();
    m = red[0];
    __syncthreads();

    // ---- exp + sum ----
    float s = 0.f;
    float ev[8];
#pragma unroll
    for (int jj = 0; jj < 8; jj++) {
        int j = tid + jj * 256;
        ev[jj] = (j < len) ? __expf(xv[jj] - m) : 0.f;
        s += ev[jj];
    }
#pragma unroll
    for (int off = 16; off; off >>= 1) s += __shfl_xor_sync(0xffffffffu, s, off);
    if (lane == 0) red[wid] = s;
    __syncthreads();
    if (tid == 0) {
        float ss = 0.f;
#pragma unroll
        for (int w = 0; w < 8; w++) ss += red[w];
        red[0] = ss;
    }
    __syncthreads();
    const float inv = 1.f / red[0];

    // ---- write A-type split [hi | lo | hi], zero above diagonal ----
#pragma unroll
    for (int jj = 0; jj < 8; jj++) {
        int j = tid + jj * 256;
        float w = ev[jj] * inv;            // 0 for j > i
        __nv_bfloat16 h, l;
        split2(w, h, l);
        o[j] = h; o[SS + j] = l; o[2 * SS + j] = h;
    }
}

// ---------------------------------------------------------------------------
// Kernel: out = P V ; K loop runs 3 causal-capped segments (hi, lo, hi parts).
// ---------------------------------------------------------------------------
__global__ __launch_bounds__(256, 2) void pv_kernel(float* __restrict__ out)
{
    const int bx = blockIdx.x, by = blockIdx.y, b = blockIdx.z;
    const __nv_bfloat16* A  = g_ps + (size_t)b * SS * S3;
    const __nv_bfloat16* Bp = g_vt + (size_t)b * DD * S3;
    const int row0 = by * TM, col0 = bx * TN;
    const int tps = (row0 + TM) / TK;      // causal cap per segment

    float acc[4][4][4];
#pragma unroll
    for (int i = 0; i < 4; i++)
#pragma unroll
        for (int j = 0; j < 4; j++)
#pragma unroll
            for (int q = 0; q < 4; q++) acc[i][j][q] = 0.f;

    gemm_core(A, row0, S3, Bp, col0, S3, 3 * tps, KSeg{tps}, acc);

    float* C = out + (size_t)b * SS * DD;
    const int lane = threadIdx.x & 31, warp = threadIdx.x >> 5;
    const int wm = (warp & 1) << 6, wn = (warp >> 1) << 5;
    const int g = lane >> 2, tig = lane & 3;

#pragma unroll
    for (int mi = 0; mi < 4; mi++)
#pragma unroll
        for (int ni = 0; ni < 4; ni++) {
            const int n = col0 + wn + (ni << 3) + (tig << 1);
#pragma unroll
            for (int rr = 0; rr < 2; rr++) {
                const int m = row0 + wm + (mi << 4) + g + rr * 8;
                float2 v;
                v.x = acc[mi][ni][rr * 2 + 0];
                v.y = acc[mi][ni][rr * 2 + 1];
                *(float2*)(C + (size_t)m * DD + n) = v;
            }
        }
}

// ---------------------------------------------------------------------------
extern "C" void kernel_launch(void* const* d_in, const int* in_sizes, int n_in,
                              void* d_out, int out_size)
{
    const float* x  = (const float*)d_in[0];
    const float* Wq = (const float*)d_in[1];
    const float* bq = (const float*)d_in[2];
    const float* Wk = (const float*)d_in[3];
    const float* bk = (const float*)d_in[4];
    const float* Wv = (const float*)d_in[5];
    const float* bv = (const float*)d_in[6];
    float* out = (float*)d_out;

    split_x_kernel<<<(MM * DD) / 256, 256>>>(x);
    split_w_kernel<<<dim3((DD * DD) / 256, 1, 3), 256>>>(Wq, Wk, Wv);
    proj_kernel<<<dim3(DD / TN, MM / TM, 3), 256>>>(bq, bk, bv);
    scores_kernel<<<dim3(SS / TN, SS / TM, BB), 256>>>();
    softmax_kernel<<<BB * SS, 256>>>();
    pv_kernel<<<dim3(DD / TN, SS / TM, BB), 256>>>(out);
}

// round 5
// speedup vs baseline: 2.4740x; 1.0608x over previous
#include <cuda_runtime.h>
#include <cuda_bf16.h>
#include <cstdint>

// Problem constants
#define BB 4
#define SS 2048
#define DD 1024
#define MM (BB*SS)       // 8192
#define K3 (3*DD)        // 3072  (split-tripled K for projections/scores)
#define S3 (3*SS)        // 6144  (split-tripled K for PV)

// GEMM tiling
#define TM 128
#define TN 128
#define TK 64
#define AST 72           // TK + 8 pad: 144B row stride (16B aligned; ldmatrix
                         // 8-row groups hit banks 4(r+c) mod 32 -> conflict-free)
#define ST 3             // cp.async pipeline stages

#define A_ELEMS (TM*AST)              // elems per A stage
#define STAGE_ELEMS (2*A_ELEMS)       // A + B
#define DYN_BYTES (ST*STAGE_ELEMS*2)  // 110592 B dynamic smem

// ---------------------------------------------------------------------------
// Scratch (__device__ globals).  A-type row = [hi|lo|hi], B-type = [hi|hi|lo]:
// plain bf16 GEMM over tripled K computes hi*hi + lo*hi + hi*lo.
// ---------------------------------------------------------------------------
__device__ __nv_bfloat16 g_xs[(size_t)MM * K3];
__device__ __nv_bfloat16 g_wq[(size_t)DD * K3];
__device__ __nv_bfloat16 g_wk[(size_t)DD * K3];
__device__ __nv_bfloat16 g_wv[(size_t)DD * K3];
__device__ __nv_bfloat16 g_qs[(size_t)MM * K3];
__device__ __nv_bfloat16 g_ks[(size_t)MM * K3];
__device__ __nv_bfloat16 g_vt[(size_t)BB * DD * S3];
__device__ float         g_sc[(size_t)BB * SS * SS];
__device__ __nv_bfloat16 g_ps[(size_t)BB * SS * S3];

__device__ __forceinline__ void split2(float v, __nv_bfloat16& h, __nv_bfloat16& l) {
    h = __float2bfloat16(v);
    l = __float2bfloat16(v - __bfloat162float(h));
}

// ---------------------------------------------------------------------------
// Split input kernels
// ---------------------------------------------------------------------------
__global__ __launch_bounds__(256) void split_x_kernel(const float* __restrict__ x)
{
    size_t idx = (size_t)blockIdx.x * 256 + threadIdx.x;
    size_t m = idx >> 10, d = idx & (DD - 1);
    __nv_bfloat16 h, l;
    split2(x[idx], h, l);
    __nv_bfloat16* r = g_xs + m * K3;
    r[d] = h; r[DD + d] = l; r[2 * DD + d] = h;            // A-type
}

__global__ __launch_bounds__(256) void split_w_kernel(
    const float* __restrict__ Wq, const float* __restrict__ Wk,
    const float* __restrict__ Wv)
{
    int z = blockIdx.z;
    size_t idx = (size_t)blockIdx.x * 256 + threadIdx.x;
    const float* W = (z == 0) ? Wq : (z == 1) ? Wk : Wv;
    __nv_bfloat16* O = (z == 0) ? g_wq : (z == 1) ? g_wk : g_wv;
    size_t e = idx >> 10, d = idx & (DD - 1);
    __nv_bfloat16 h, l;
    split2(W[idx], h, l);
    __nv_bfloat16* r = O + e * K3;
    r[d] = h; r[DD + d] = h; r[2 * DD + d] = l;            // B-type
}

// ---------------------------------------------------------------------------
// GEMM core: C[128x128] = A[row0..][.] * B[col0..][.]^T, bf16 K-major
// operands.  TK=64 tiles, 3-stage cp.async ring issued 2 tiles ahead,
// register double-buffered ldmatrix fragments, mma.sync m16n8k16.
// ---------------------------------------------------------------------------
struct KLin {
    __device__ __forceinline__ int operator()(int t) const { return t * TK; }
};
struct KSeg {
    int tps;  // tiles per segment
    __device__ __forceinline__ int operator()(int t) const {
        int s = t / tps; return s * SS + (t - s * tps) * TK;
    }
};

#define LDSM_X4(r0, r1, r2, r3, addr) \
    asm volatile("ldmatrix.sync.aligned.m8n8.x4.shared.b16 {%0,%1,%2,%3}, [%4];" \
                 : "=r"(r0), "=r"(r1), "=r"(r2), "=r"(r3) : "r"(addr))

template <typename KF>
__device__ __forceinline__ void gemm_core(
    const __nv_bfloat16* __restrict__ A, int row0, size_t lda,
    const __nv_bfloat16* __restrict__ B, int col0, size_t ldb,
    int ntiles, KF koff, float acc[4][4][4])
{
    extern __shared__ __align__(16) __nv_bfloat16 smem[];

    const int tid  = threadIdx.x;
    const int lane = tid & 31, warp = tid >> 5;
    const int wm = (warp & 1) << 6;       // 0/64
    const int wn = (warp >> 1) << 5;      // 0/32/64/96
    const int lr  = lane & 7;
    const int seg = lane >> 3;            // 0..3
    const int lrow = tid >> 3;            // loader row base 0..31
    const int lcol = (tid & 7) << 3;      // loader elem col 0..56

    // ldmatrix lane-address bases (bytes) per pipeline stage
    uint32_t aBase[ST], bBase[ST];
#pragma unroll
    for (int s = 0; s < ST; s++) {
        aBase[s] = (uint32_t)__cvta_generic_to_shared(
            smem + s * STAGE_ELEMS + (wm + ((seg & 1) << 3) + lr) * AST + ((seg >> 1) << 3));
        bBase[s] = (uint32_t)__cvta_generic_to_shared(
            smem + s * STAGE_ELEMS + A_ELEMS + (wn + ((seg >> 1) << 3) + lr) * AST + ((seg & 1) << 3));
    }

    auto LDT = [&](int t) {
        const int ko = koff(t);
        __nv_bfloat16* as = smem + (t % ST) * STAGE_ELEMS;
        __nv_bfloat16* bs = as + A_ELEMS;
#pragma unroll
        for (int i = 0; i < 4; i++) {
            const int r = lrow + (i << 5);
            const void* sa = (const void*)(A + (size_t)(row0 + r) * lda + ko + lcol);
            uint32_t da = (uint32_t)__cvta_generic_to_shared(&as[r * AST + lcol]);
            asm volatile("cp.async.cg.shared.global [%0], [%1], 16;" :: "r"(da), "l"(sa));
            const void* sb = (const void*)(B + (size_t)(col0 + r) * ldb + ko + lcol);
            uint32_t db = (uint32_t)__cvta_generic_to_shared(&bs[r * AST + lcol]);
            asm volatile("cp.async.cg.shared.global [%0], [%1], 16;" :: "r"(db), "l"(sb));
        }
        asm volatile("cp.async.commit_group;" ::: "memory");
    };

    LDT(0);
    if (ntiles > 1) LDT(1);

    uint32_t af[2][4][4], bf[2][2][4];

    for (int t = 0; t < ntiles; t++) {
        if (t + 2 < ntiles) LDT(t + 2);    // stage (t+2)%ST: free since iter t-1

        if (t + 3 <= ntiles)      asm volatile("cp.async.wait_group 2;" ::: "memory");
        else if (t + 2 == ntiles) asm volatile("cp.async.wait_group 1;" ::: "memory");
        else                      asm volatile("cp.async.wait_group 0;" ::: "memory");
        __syncthreads();

        const int st = t % ST;
        const uint32_t ab = aBase[st], bb = bBase[st];

        // prefetch k-step 0 fragments
#pragma unroll
        for (int mi = 0; mi < 4; mi++)
            LDSM_X4(af[0][mi][0], af[0][mi][1], af[0][mi][2], af[0][mi][3],
                    ab + mi * (16 * AST * 2));
#pragma unroll
        for (int n2 = 0; n2 < 2; n2++)
            LDSM_X4(bf[0][n2][0], bf[0][n2][1], bf[0][n2][2], bf[0][n2][3],
                    bb + n2 * (16 * AST * 2));

#pragma unroll
        for (int kk = 0; kk < 4; kk++) {
            const int cur = kk & 1, nxt = cur ^ 1;
            if (kk < 3) {                  // prefetch next k-step
                const uint32_t ak = ab + (kk + 1) * 32;
                const uint32_t bk = bb + (kk + 1) * 32;
#pragma unroll
                for (int mi = 0; mi < 4; mi++)
                    LDSM_X4(af[nxt][mi][0], af[nxt][mi][1], af[nxt][mi][2], af[nxt][mi][3],
                            ak + mi * (16 * AST * 2));
#pragma unroll
                for (int n2 = 0; n2 < 2; n2++)
                    LDSM_X4(bf[nxt][n2][0], bf[nxt][n2][1], bf[nxt][n2][2], bf[nxt][n2][3],
                            bk + n2 * (16 * AST * 2));
            }
#pragma unroll
            for (int mi = 0; mi < 4; mi++)
#pragma unroll
                for (int ni = 0; ni < 4; ni++) {
                    float* c = acc[mi][ni];
                    const uint32_t b0 = bf[cur][ni >> 1][(ni & 1) << 1];
                    const uint32_t b1 = bf[cur][ni >> 1][((ni & 1) << 1) + 1];
                    asm volatile(
                        "mma.sync.aligned.m16n8k16.row.col.f32.bf16.bf16.f32 "
                        "{%0,%1,%2,%3}, {%4,%5,%6,%7}, {%8,%9}, {%0,%1,%2,%3};\n"
                        : "+f"(c[0]), "+f"(c[1]), "+f"(c[2]), "+f"(c[3])
                        : "r"(af[cur][mi][0]), "r"(af[cur][mi][1]),
                          "r"(af[cur][mi][2]), "r"(af[cur][mi][3]),
                          "r"(b0), "r"(b1));
                }
        }
        __syncthreads();
    }
}

// ---------------------------------------------------------------------------
// Kernel: QKV projections (z = 0/1/2 -> Q/K/V), epilogue writes bf16 splits.
// ---------------------------------------------------------------------------
__global__ __launch_bounds__(256) void proj_kernel(
    const float* __restrict__ bq, const float* __restrict__ bk,
    const float* __restrict__ bv)
{
    const int z = blockIdx.z;
    const __nv_bfloat16* W = (z == 0) ? g_wq : (z == 1) ? g_wk : g_wv;
    const float* bias      = (z == 0) ? bq   : (z == 1) ? bk   : bv;
    const int row0 = blockIdx.y * TM, col0 = blockIdx.x * TN;

    float acc[4][4][4];
#pragma unroll
    for (int i = 0; i < 4; i++)
#pragma unroll
        for (int j = 0; j < 4; j++)
#pragma unroll
            for (int q = 0; q < 4; q++) acc[i][j][q] = 0.f;

    gemm_core(g_xs, row0, K3, W, col0, K3, K3 / TK, KLin{}, acc);

    const int lane = threadIdx.x & 31, warp = threadIdx.x >> 5;
    const int wm = (warp & 1) << 6, wn = (warp >> 1) << 5;
    const int g = lane >> 2, tig = lane & 3;

#pragma unroll
    for (int mi = 0; mi < 4; mi++)
#pragma unroll
        for (int ni = 0; ni < 4; ni++) {
            const int n = col0 + wn + (ni << 3) + (tig << 1);
            const float b0 = bias[n], b1 = bias[n + 1];
#pragma unroll
            for (int rr = 0; rr < 2; rr++) {
                const int m = row0 + wm + (mi << 4) + g + rr * 8;
                float v0 = acc[mi][ni][rr * 2 + 0] + b0;
                float v1 = acc[mi][ni][rr * 2 + 1] + b1;
                __nv_bfloat16 h0, l0, h1, l1;
                split2(v0, h0, l0); split2(v1, h1, l1);
                if (z == 0) {          // Q: A-type [hi|lo|hi]
                    __nv_bfloat16* r = g_qs + (size_t)m * K3 + n;
                    __nv_bfloat162 th; th.x = h0; th.y = h1;
                    __nv_bfloat162 tl; tl.x = l0; tl.y = l1;
                    *(__nv_bfloat162*)(r)          = th;
                    *(__nv_bfloat162*)(r + DD)     = tl;
                    *(__nv_bfloat162*)(r + 2 * DD) = th;
                } else if (z == 1) {   // K: B-type [hi|hi|lo]
                    __nv_bfloat16* r = g_ks + (size_t)m * K3 + n;
                    __nv_bfloat162 th; th.x = h0; th.y = h1;
                    __nv_bfloat162 tl; tl.x = l0; tl.y = l1;
                    *(__nv_bfloat162*)(r)          = th;
                    *(__nv_bfloat162*)(r + DD)     = th;
                    *(__nv_bfloat162*)(r + 2 * DD) = tl;
                } else {               // V: transposed into g_vt[b][d][3S], B-type
                    const int b = m >> 11, s = m & (SS - 1);
                    __nv_bfloat16* r0 = g_vt + ((size_t)b * DD + n) * S3 + s;
                    r0[0] = h0; r0[SS] = h0; r0[2 * SS] = l0;
                    __nv_bfloat16* r1 = g_vt + ((size_t)b * DD + n + 1) * S3 + s;
                    r1[0] = h1; r1[SS] = h1; r1[2 * SS] = l1;
                }
            }
        }
}

// ---------------------------------------------------------------------------
// Kernel: scores = Q K^T / sqrt(D); causal upper blocks skipped entirely.
// ---------------------------------------------------------------------------
__global__ __launch_bounds__(256) void scores_kernel()
{
    const int bx = blockIdx.x, by = blockIdx.y, b = blockIdx.z;
    if (bx > by) return;
    const __nv_bfloat16* A  = g_qs + (size_t)b * SS * K3;
    const __nv_bfloat16* Bp = g_ks + (size_t)b * SS * K3;
    const int row0 = by * TM, col0 = bx * TN;

    float acc[4][4][4];
#pragma unroll
    for (int i = 0; i < 4; i++)
#pragma unroll
        for (int j = 0; j < 4; j++)
#pragma unroll
            for (int q = 0; q < 4; q++) acc[i][j][q] = 0.f;

    gemm_core(A, row0, K3, Bp, col0, K3, K3 / TK, KLin{}, acc);

    float* C = g_sc + (size_t)b * SS * SS;
    const int lane = threadIdx.x & 31, warp = threadIdx.x >> 5;
    const int wm = (warp & 1) << 6, wn = (warp >> 1) << 5;
    const int g = lane >> 2, tig = lane & 3;

#pragma unroll
    for (int mi = 0; mi < 4; mi++)
#pragma unroll
        for (int ni = 0; ni < 4; ni++) {
            const int n = col0 + wn + (ni << 3) + (tig << 1);
#pragma unroll
            for (int rr = 0; rr < 2; rr++) {
                const int m = row0 + wm + (mi << 4) + g + rr * 8;
                float2 v;
                v.x = acc[mi][ni][rr * 2 + 0] * 0.03125f;
                v.y = acc[mi][ni][rr * 2 + 1] * 0.03125f;
                *(float2*)(C + (size_t)m * SS + n) = v;
            }
        }
}

// ---------------------------------------------------------------------------
// Kernel: causal row softmax; writes split weights (A-type) with zero fill.
// ---------------------------------------------------------------------------
__global__ __launch_bounds__(256) void softmax_kernel()
{
    const int row = blockIdx.x;
    const int b = row >> 11;
    const int i = row & (SS - 1);
    const float* p = g_sc + (size_t)b * SS * SS + (size_t)i * SS;
    __nv_bfloat16* o = g_ps + (size_t)b * SS * S3 + (size_t)i * S3;
    const int len = i + 1;
    const int tid = threadIdx.x;
    const int lane = tid & 31, wid = tid >> 5;
    __shared__ float red[8];

    float m = __int_as_float(0xff800000);
    float xv[8];
#pragma unroll
    for (int jj = 0; jj < 8; jj++) {
        int j = tid + jj * 256;
        xv[jj] = (j < len) ? p[j] : __int_as_float(0xff800000);
        m = fmaxf(m, xv[jj]);
    }
#pragma unroll
    for (int off = 16; off; off >>= 1) m = fmaxf(m, __shfl_xor_sync(0xffffffffu, m, off));
    if (lane == 0) red[wid] = m;
    __syncthreads();
    if (tid == 0) {
        float mm = red[0];
#pragma unroll
        for (int w = 1; w < 8; w++) mm = fmaxf(mm, red[w]);
        red[0] = mm;
    }
    __syncthreads();
    m = red[0];
    __syncthreads();

    float s = 0.f;
    float ev[8];
#pragma unroll
    for (int jj = 0; jj < 8; jj++) {
        int j = tid + jj * 256;
        ev[jj] = (j < len) ? __expf(xv[jj] - m) : 0.f;
        s += ev[jj];
    }
#pragma unroll
    for (int off = 16; off; off >>= 1) s += __shfl_xor_sync(0xffffffffu, s, off);
    if (lane == 0) red[wid] = s;
    __syncthreads();
    if (tid == 0) {
        float ss = 0.f;
#pragma unroll
        for (int w = 0; w < 8; w++) ss += red[w];
        red[0] = ss;
    }
    __syncthreads();
    const float inv = 1.f / red[0];

#pragma unroll
    for (int jj = 0; jj < 8; jj++) {
        int j = tid + jj * 256;
        float w = ev[jj] * inv;
        __nv_bfloat16 h, l;
        split2(w, h, l);
        o[j] = h; o[SS + j] = l; o[2 * SS + j] = h;        // A-type
    }
}

// ---------------------------------------------------------------------------
// Kernel: out = P V ; K runs 3 causal-capped segments (hi, lo, hi parts).
// ---------------------------------------------------------------------------
__global__ __launch_bounds__(256) void pv_kernel(float* __restrict__ out)
{
    const int bx = blockIdx.x, by = blockIdx.y, b = blockIdx.z;
    const __nv_bfloat16* A  = g_ps + (size_t)b * SS * S3;
    const __nv_bfloat16* Bp = g_vt + (size_t)b * DD * S3;
    const int row0 = by * TM, col0 = bx * TN;
    const int tps = (row0 + TM) / TK;      // causal cap per segment

    float acc[4][4][4];
#pragma unroll
    for (int i = 0; i < 4; i++)
#pragma unroll
        for (int j = 0; j < 4; j++)
#pragma unroll
            for (int q = 0; q < 4; q++) acc[i][j][q] = 0.f;

    gemm_core(A, row0, S3, Bp, col0, S3, 3 * tps, KSeg{tps}, acc);

    float* C = out + (size_t)b * SS * DD;
    const int lane = threadIdx.x & 31, warp = threadIdx.x >> 5;
    const int wm = (warp & 1) << 6, wn = (warp >> 1) << 5;
    const int g = lane >> 2, tig = lane & 3;

#pragma unroll
    for (int mi = 0; mi < 4; mi++)
#pragma unroll
        for (int ni = 0; ni < 4; ni++) {
            const int n = col0 + wn + (ni << 3) + (tig << 1);
#pragma unroll
            for (int rr = 0; rr < 2; rr++) {
                const int m = row0 + wm + (mi << 4) + g + rr * 8;
                float2 v;
                v.x = acc[mi][ni][rr * 2 + 0];
                v.y = acc[mi][ni][rr * 2 + 1];
                *(float2*)(C + (size_t)m * DD + n) = v;
            }
        }
}

// ---------------------------------------------------------------------------
extern "C" void kernel_launch(void* const* d_in, const int* in_sizes, int n_in,
                              void* d_out, int out_size)
{
    const float* x  = (const float*)d_in[0];
    const float* Wq = (const float*)d_in[1];
    const float* bq = (const float*)d_in[2];
    const float* Wk = (const float*)d_in[3];
    const float* bk = (const float*)d_in[4];
    const float* Wv = (const float*)d_in[5];
    const float* bv = (const float*)d_in[6];
    float* out = (float*)d_out;

    cudaFuncSetAttribute(proj_kernel,   cudaFuncAttributeMaxDynamicSharedMemorySize, DYN_BYTES);
    cudaFuncSetAttribute(scores_kernel, cudaFuncAttributeMaxDynamicSharedMemorySize, DYN_BYTES);
    cudaFuncSetAttribute(pv_kernel,     cudaFuncAttributeMaxDynamicSharedMemorySize, DYN_BYTES);

    split_x_kernel<<<(MM * DD) / 256, 256>>>(x);
    split_w_kernel<<<dim3((DD * DD) / 256, 1, 3), 256>>>(Wq, Wk, Wv);
    proj_kernel<<<dim3(DD / TN, MM / TM, 3), 256, DYN_BYTES>>>(bq, bk, bv);
    scores_kernel<<<dim3(SS / TN, SS / TM, BB), 256, DYN_BYTES>>>();
    softmax_kernel<<<BB * SS, 256>>>();
    pv_kernel<<<dim3(DD / TN, SS / TM, BB), 256, DYN_BYTES>>>(out);
}

// round 6
// speedup vs baseline: 2.4806x; 1.0026x over previous
#include <cuda_runtime.h>
#include <cuda_bf16.h>
#include <cstdint>

// Problem constants
#define BB 4
#define SS 2048
#define DD 1024
#define MM (BB*SS)       // 8192
#define K3 (3*DD)        // 3072  (split-tripled K for projections/scores)
#define S3 (3*SS)        // 6144  (split-tripled K for PV)

// GEMM tiling
#define TM 128
#define TN 128
#define TK 64
#define AST 72           // TK + 8 pad: 144B row stride (16B aligned; ldmatrix
                         // 8-row groups conflict-free)
#define ST 2             // cp.async pipeline stages (2 => 73.7KB smem => 2 CTA/SM)

#define A_ELEMS (TM*AST)              // elems per A stage
#define STAGE_ELEMS (2*A_ELEMS)       // A + B
#define DYN_BYTES (ST*STAGE_ELEMS*2)  // 73728 B dynamic smem

// ---------------------------------------------------------------------------
// Scratch (__device__ globals).  A-type row = [hi|lo|hi], B-type = [hi|hi|lo]:
// plain bf16 GEMM over tripled K computes hi*hi + lo*hi + hi*lo.
// ---------------------------------------------------------------------------
__device__ __nv_bfloat16 g_xs[(size_t)MM * K3];
__device__ __nv_bfloat16 g_wq[(size_t)DD * K3];
__device__ __nv_bfloat16 g_wk[(size_t)DD * K3];
__device__ __nv_bfloat16 g_wv[(size_t)DD * K3];
__device__ __nv_bfloat16 g_qs[(size_t)MM * K3];
__device__ __nv_bfloat16 g_ks[(size_t)MM * K3];
__device__ __nv_bfloat16 g_vt[(size_t)BB * DD * S3];
__device__ float         g_sc[(size_t)BB * SS * SS];
__device__ __nv_bfloat16 g_ps[(size_t)BB * SS * S3];

__device__ __forceinline__ void split2(float v, __nv_bfloat16& h, __nv_bfloat16& l) {
    h = __float2bfloat16(v);
    l = __float2bfloat16(v - __bfloat162float(h));
}

// ---------------------------------------------------------------------------
// Split input kernels
// ---------------------------------------------------------------------------
__global__ __launch_bounds__(256) void split_x_kernel(const float* __restrict__ x)
{
    size_t idx = (size_t)blockIdx.x * 256 + threadIdx.x;
    size_t m = idx >> 10, d = idx & (DD - 1);
    __nv_bfloat16 h, l;
    split2(x[idx], h, l);
    __nv_bfloat16* r = g_xs + m * K3;
    r[d] = h; r[DD + d] = l; r[2 * DD + d] = h;            // A-type
}

__global__ __launch_bounds__(256) void split_w_kernel(
    const float* __restrict__ Wq, const float* __restrict__ Wk,
    const float* __restrict__ Wv)
{
    int z = blockIdx.z;
    size_t idx = (size_t)blockIdx.x * 256 + threadIdx.x;
    const float* W = (z == 0) ? Wq : (z == 1) ? Wk : Wv;
    __nv_bfloat16* O = (z == 0) ? g_wq : (z == 1) ? g_wk : g_wv;
    size_t e = idx >> 10, d = idx & (DD - 1);
    __nv_bfloat16 h, l;
    split2(W[idx], h, l);
    __nv_bfloat16* r = O + e * K3;
    r[d] = h; r[DD + d] = h; r[2 * DD + d] = l;            // B-type
}

// ---------------------------------------------------------------------------
// GEMM core: C[128x128] = A[row0..][.] * B[col0..][.]^T, bf16 K-major
// operands.  TK=64 tiles, 2-stage cp.async ring, ONE barrier per tile,
// register double-buffered ldmatrix fragments, mma.sync m16n8k16.
// Designed for 2 CTAs/SM: cross-CTA interleave hides sync/mem bubbles.
// ---------------------------------------------------------------------------
struct KLin {
    __device__ __forceinline__ int operator()(int t) const { return t * TK; }
};
struct KSeg {
    int tps;  // tiles per segment
    __device__ __forceinline__ int operator()(int t) const {
        int s = t / tps; return s * SS + (t - s * tps) * TK;
    }
};

#define LDSM_X4(r0, r1, r2, r3, addr) \
    asm volatile("ldmatrix.sync.aligned.m8n8.x4.shared.b16 {%0,%1,%2,%3}, [%4];" \
                 : "=r"(r0), "=r"(r1), "=r"(r2), "=r"(r3) : "r"(addr))

template <typename KF>
__device__ __forceinline__ void gemm_core(
    const __nv_bfloat16* __restrict__ A, int row0, size_t lda,
    const __nv_bfloat16* __restrict__ B, int col0, size_t ldb,
    int ntiles, KF koff, float acc[4][4][4])
{
    extern __shared__ __align__(16) __nv_bfloat16 smem[];

    const int tid  = threadIdx.x;
    const int lane = tid & 31, warp = tid >> 5;
    const int wm = (warp & 1) << 6;       // 0/64
    const int wn = (warp >> 1) << 5;      // 0/32/64/96
    const int lr  = lane & 7;
    const int seg = lane >> 3;            // 0..3
    const int lrow = tid >> 3;            // loader row base 0..31
    const int lcol = (tid & 7) << 3;      // loader elem col 0..56

    // ldmatrix lane-address bases (bytes) per pipeline stage
    uint32_t aBase[ST], bBase[ST];
#pragma unroll
    for (int s = 0; s < ST; s++) {
        aBase[s] = (uint32_t)__cvta_generic_to_shared(
            smem + s * STAGE_ELEMS + (wm + ((seg & 1) << 3) + lr) * AST + ((seg >> 1) << 3));
        bBase[s] = (uint32_t)__cvta_generic_to_shared(
            smem + s * STAGE_ELEMS + A_ELEMS + (wn + ((seg >> 1) << 3) + lr) * AST + ((seg & 1) << 3));
    }

    auto LDT = [&](int t) {
        const int ko = koff(t);
        __nv_bfloat16* as = smem + (t & 1) * STAGE_ELEMS;
        __nv_bfloat16* bs = as + A_ELEMS;
#pragma unroll
        for (int i = 0; i < 4; i++) {
            const int r = lrow + (i << 5);
            const void* sa = (const void*)(A + (size_t)(row0 + r) * lda + ko + lcol);
            uint32_t da = (uint32_t)__cvta_generic_to_shared(&as[r * AST + lcol]);
            asm volatile("cp.async.cg.shared.global [%0], [%1], 16;" :: "r"(da), "l"(sa));
            const void* sb = (const void*)(B + (size_t)(col0 + r) * ldb + ko + lcol);
            uint32_t db = (uint32_t)__cvta_generic_to_shared(&bs[r * AST + lcol]);
            asm volatile("cp.async.cg.shared.global [%0], [%1], 16;" :: "r"(db), "l"(sb));
        }
        asm volatile("cp.async.commit_group;" ::: "memory");
    };

    LDT(0);

    uint32_t af[2][4][4], bf[2][2][4];

    for (int t = 0; t < ntiles; t++) {
        asm volatile("cp.async.wait_group 0;" ::: "memory");
        __syncthreads();                   // stage t visible; all warps done with t-1
        if (t + 1 < ntiles) LDT(t + 1);    // overwrites stage consumed at t-1

        const uint32_t ab = aBase[t & 1], bb = bBase[t & 1];

        // prefetch k-step 0 fragments
#pragma unroll
        for (int mi = 0; mi < 4; mi++)
            LDSM_X4(af[0][mi][0], af[0][mi][1], af[0][mi][2], af[0][mi][3],
                    ab + mi * (16 * AST * 2));
#pragma unroll
        for (int n2 = 0; n2 < 2; n2++)
            LDSM_X4(bf[0][n2][0], bf[0][n2][1], bf[0][n2][2], bf[0][n2][3],
                    bb + n2 * (16 * AST * 2));

#pragma unroll
        for (int kk = 0; kk < 4; kk++) {
            const int cur = kk & 1, nxt = cur ^ 1;
            if (kk < 3) {                  // prefetch next k-step
                const uint32_t ak = ab + (kk + 1) * 32;
                const uint32_t bk = bb + (kk + 1) * 32;
#pragma unroll
                for (int mi = 0; mi < 4; mi++)
                    LDSM_X4(af[nxt][mi][0], af[nxt][mi][1], af[nxt][mi][2], af[nxt][mi][3],
                            ak + mi * (16 * AST * 2));
#pragma unroll
                for (int n2 = 0; n2 < 2; n2++)
                    LDSM_X4(bf[nxt][n2][0], bf[nxt][n2][1], bf[nxt][n2][2], bf[nxt][n2][3],
                            bk + n2 * (16 * AST * 2));
            }
#pragma unroll
            for (int mi = 0; mi < 4; mi++)
#pragma unroll
                for (int ni = 0; ni < 4; ni++) {
                    float* c = acc[mi][ni];
                    const uint32_t b0 = bf[cur][ni >> 1][(ni & 1) << 1];
                    const uint32_t b1 = bf[cur][ni >> 1][((ni & 1) << 1) + 1];
                    asm volatile(
                        "mma.sync.aligned.m16n8k16.row.col.f32.bf16.bf16.f32 "
                        "{%0,%1,%2,%3}, {%4,%5,%6,%7}, {%8,%9}, {%0,%1,%2,%3};\n"
                        : "+f"(c[0]), "+f"(c[1]), "+f"(c[2]), "+f"(c[3])
                        : "r"(af[cur][mi][0]), "r"(af[cur][mi][1]),
                          "r"(af[cur][mi][2]), "r"(af[cur][mi][3]),
                          "r"(b0), "r"(b1));
                }
        }
    }
    __syncthreads();
}

// ---------------------------------------------------------------------------
// Kernel: QKV projections (z = 0/1/2 -> Q/K/V), epilogue writes bf16 splits.
// ---------------------------------------------------------------------------
__global__ __launch_bounds__(256, 2) void proj_kernel(
    const float* __restrict__ bq, const float* __restrict__ bk,
    const float* __restrict__ bv)
{
    const int z = blockIdx.z;
    const __nv_bfloat16* W = (z == 0) ? g_wq : (z == 1) ? g_wk : g_wv;
    const float* bias      = (z == 0) ? bq   : (z == 1) ? bk   : bv;
    const int row0 = blockIdx.y * TM, col0 = blockIdx.x * TN;

    float acc[4][4][4];
#pragma unroll
    for (int i = 0; i < 4; i++)
#pragma unroll
        for (int j = 0; j < 4; j++)
#pragma unroll
            for (int q = 0; q < 4; q++) acc[i][j][q] = 0.f;

    gemm_core(g_xs, row0, K3, W, col0, K3, K3 / TK, KLin{}, acc);

    const int lane = threadIdx.x & 31, warp = threadIdx.x >> 5;
    const int wm = (warp & 1) << 6, wn = (warp >> 1) << 5;
    const int g = lane >> 2, tig = lane & 3;

#pragma unroll
    for (int mi = 0; mi < 4; mi++)
#pragma unroll
        for (int ni = 0; ni < 4; ni++) {
            const int n = col0 + wn + (ni << 3) + (tig << 1);
            const float b0 = bias[n], b1 = bias[n + 1];
#pragma unroll
            for (int rr = 0; rr < 2; rr++) {
                const int m = row0 + wm + (mi << 4) + g + rr * 8;
                float v0 = acc[mi][ni][rr * 2 + 0] + b0;
                float v1 = acc[mi][ni][rr * 2 + 1] + b1;
                __nv_bfloat16 h0, l0, h1, l1;
                split2(v0, h0, l0); split2(v1, h1, l1);
                if (z == 0) {          // Q: A-type [hi|lo|hi]
                    __nv_bfloat16* r = g_qs + (size_t)m * K3 + n;
                    __nv_bfloat162 th; th.x = h0; th.y = h1;
                    __nv_bfloat162 tl; tl.x = l0; tl.y = l1;
                    *(__nv_bfloat162*)(r)          = th;
                    *(__nv_bfloat162*)(r + DD)     = tl;
                    *(__nv_bfloat162*)(r + 2 * DD) = th;
                } else if (z == 1) {   // K: B-type [hi|hi|lo]
                    __nv_bfloat16* r = g_ks + (size_t)m * K3 + n;
                    __nv_bfloat162 th; th.x = h0; th.y = h1;
                    __nv_bfloat162 tl; tl.x = l0; tl.y = l1;
                    *(__nv_bfloat162*)(r)          = th;
                    *(__nv_bfloat162*)(r + DD)     = th;
                    *(__nv_bfloat162*)(r + 2 * DD) = tl;
                } else {               // V: transposed into g_vt[b][d][3S], B-type
                    const int b = m >> 11, s = m & (SS - 1);
                    __nv_bfloat16* r0 = g_vt + ((size_t)b * DD + n) * S3 + s;
                    r0[0] = h0; r0[SS] = h0; r0[2 * SS] = l0;
                    __nv_bfloat16* r1 = g_vt + ((size_t)b * DD + n + 1) * S3 + s;
                    r1[0] = h1; r1[SS] = h1; r1[2 * SS] = l1;
                }
            }
        }
}

// ---------------------------------------------------------------------------
// Kernel: scores = Q K^T / sqrt(D); causal upper blocks skipped entirely.
// ---------------------------------------------------------------------------
__global__ __launch_bounds__(256, 2) void scores_kernel()
{
    const int bx = blockIdx.x, by = blockIdx.y, b = blockIdx.z;
    if (bx > by) return;
    const __nv_bfloat16* A  = g_qs + (size_t)b * SS * K3;
    const __nv_bfloat16* Bp = g_ks + (size_t)b * SS * K3;
    const int row0 = by * TM, col0 = bx * TN;

    float acc[4][4][4];
#pragma unroll
    for (int i = 0; i < 4; i++)
#pragma unroll
        for (int j = 0; j < 4; j++)
#pragma unroll
            for (int q = 0; q < 4; q++) acc[i][j][q] = 0.f;

    gemm_core(A, row0, K3, Bp, col0, K3, K3 / TK, KLin{}, acc);

    float* C = g_sc + (size_t)b * SS * SS;
    const int lane = threadIdx.x & 31, warp = threadIdx.x >> 5;
    const int wm = (warp & 1) << 6, wn = (warp >> 1) << 5;
    const int g = lane >> 2, tig = lane & 3;

#pragma unroll
    for (int mi = 0; mi < 4; mi++)
#pragma unroll
        for (int ni = 0; ni < 4; ni++) {
            const int n = col0 + wn + (ni << 3) + (tig << 1);
#pragma unroll
            for (int rr = 0; rr < 2; rr++) {
                const int m = row0 + wm + (mi << 4) + g + rr * 8;
                float2 v;
                v.x = acc[mi][ni][rr * 2 + 0] * 0.03125f;
                v.y = acc[mi][ni][rr * 2 + 1] * 0.03125f;
                *(float2*)(C + (size_t)m * SS + n) = v;
            }
        }
}

// ---------------------------------------------------------------------------
// Kernel: causal row softmax; writes split weights (A-type) with zero fill.
// ---------------------------------------------------------------------------
__global__ __launch_bounds__(256) void softmax_kernel()
{
    const int row = blockIdx.x;
    const int b = row >> 11;
    const int i = row & (SS - 1);
    const float* p = g_sc + (size_t)b * SS * SS + (size_t)i * SS;
    __nv_bfloat16* o = g_ps + (size_t)b * SS * S3 + (size_t)i * S3;
    const int len = i + 1;
    const int tid = threadIdx.x;
    const int lane = tid & 31, wid = tid >> 5;
    __shared__ float red[8];

    float m = __int_as_float(0xff800000);
    float xv[8];
#pragma unroll
    for (int jj = 0; jj < 8; jj++) {
        int j = tid + jj * 256;
        xv[jj] = (j < len) ? p[j] : __int_as_float(0xff800000);
        m = fmaxf(m, xv[jj]);
    }
#pragma unroll
    for (int off = 16; off; off >>= 1) m = fmaxf(m, __shfl_xor_sync(0xffffffffu, m, off));
    if (lane == 0) red[wid] = m;
    __syncthreads();
    if (tid == 0) {
        float mm = red[0];
#pragma unroll
        for (int w = 1; w < 8; w++) mm = fmaxf(mm, red[w]);
        red[0] = mm;
    }
    __syncthreads();
    m = red[0];
    __syncthreads();

    float s = 0.f;
    float ev[8];
#pragma unroll
    for (int jj = 0; jj < 8; jj++) {
        int j = tid + jj * 256;
        ev[jj] = (j < len) ? __expf(xv[jj] - m) : 0.f;
        s += ev[jj];
    }
#pragma unroll
    for (int off = 16; off; off >>= 1) s += __shfl_xor_sync(0xffffffffu, s, off);
    if (lane == 0) red[wid] = s;
    __syncthreads();
    if (tid == 0) {
        float ss = 0.f;
#pragma unroll
        for (int w = 0; w < 8; w++) ss += red[w];
        red[0] = ss;
    }
    __syncthreads();
    const float inv = 1.f / red[0];

#pragma unroll
    for (int jj = 0; jj < 8; jj++) {
        int j = tid + jj * 256;
        float w = ev[jj] * inv;
        __nv_bfloat16 h, l;
        split2(w, h, l);
        o[j] = h; o[SS + j] = l; o[2 * SS + j] = h;        // A-type
    }
}

// ---------------------------------------------------------------------------
// Kernel: out = P V ; K runs 3 causal-capped segments (hi, lo, hi parts).
// ---------------------------------------------------------------------------
__global__ __launch_bounds__(256, 2) void pv_kernel(float* __restrict__ out)
{
    const int bx = blockIdx.x, by = blockIdx.y, b = blockIdx.z;
    const __nv_bfloat16* A  = g_ps + (size_t)b * SS * S3;
    const __nv_bfloat16* Bp = g_vt + (size_t)b * DD * S3;
    const int row0 = by * TM, col0 = bx * TN;
    const int tps = (row0 + TM) / TK;      // causal cap per segment

    float acc[4][4][4];
#pragma unroll
    for (int i = 0; i < 4; i++)
#pragma unroll
        for (int j = 0; j < 4; j++)
#pragma unroll
            for (int q = 0; q < 4; q++) acc[i][j][q] = 0.f;

    gemm_core(A, row0, S3, Bp, col0, S3, 3 * tps, KSeg{tps}, acc);

    float* C = out + (size_t)b * SS * DD;
    const int lane = threadIdx.x & 31, warp = threadIdx.x >> 5;
    const int wm = (warp & 1) << 6, wn = (warp >> 1) << 5;
    const int g = lane >> 2, tig = lane & 3;

#pragma unroll
    for (int mi = 0; mi < 4; mi++)
#pragma unroll
        for (int ni = 0; ni < 4; ni++) {
            const int n = col0 + wn + (ni << 3) + (tig << 1);
#pragma unroll
            for (int rr = 0; rr < 2; rr++) {
                const int m = row0 + wm + (mi << 4) + g + rr * 8;
                float2 v;
                v.x = acc[mi][ni][rr * 2 + 0];
                v.y = acc[mi][ni][rr * 2 + 1];
                *(float2*)(C + (size_t)m * DD + n) = v;
            }
        }
}

// ---------------------------------------------------------------------------
extern "C" void kernel_launch(void* const* d_in, const int* in_sizes, int n_in,
                              void* d_out, int out_size)
{
    const float* x  = (const float*)d_in[0];
    const float* Wq = (const float*)d_in[1];
    const float* bq = (const float*)d_in[2];
    const float* Wk = (const float*)d_in[3];
    const float* bk = (const float*)d_in[4];
    const float* Wv = (const float*)d_in[5];
    const float* bv = (const float*)d_in[6];
    float* out = (float*)d_out;

    cudaFuncSetAttribute(proj_kernel,   cudaFuncAttributeMaxDynamicSharedMemorySize, DYN_BYTES);
    cudaFuncSetAttribute(scores_kernel, cudaFuncAttributeMaxDynamicSharedMemorySize, DYN_BYTES);
    cudaFuncSetAttribute(pv_kernel,     cudaFuncAttributeMaxDynamicSharedMemorySize, DYN_BYTES);

    split_x_kernel<<<(MM * DD) / 256, 256>>>(x);
    split_w_kernel<<<dim3((DD * DD) / 256, 1, 3), 256>>>(Wq, Wk, Wv);
    proj_kernel<<<dim3(DD / TN, MM / TM, 3), 256, DYN_BYTES>>>(bq, bk, bv);
    scores_kernel<<<dim3(SS / TN, SS / TM, BB), 256, DYN_BYTES>>>();
    softmax_kernel<<<BB * SS, 256>>>();
    pv_kernel<<<dim3(DD / TN, SS / TM, BB), 256, DYN_BYTES>>>(out);
}

// round 8
// speedup vs baseline: 2.7497x; 1.1085x over previous
#include <cuda_runtime.h>
#include <cuda_bf16.h>
#include <cstdint>

// Problem constants
#define BB 4
#define SS 2048
#define DD 1024
#define MM (BB*SS)       // 8192
#define K3 (3*DD)        // 3072  (split-tripled K for projections/scores)
#define S3 (3*SS)        // 6144  (split-tripled K for PV)

// GEMM tiling
#define TM 128
#define TN 128
#define TK 64
#define AST 72           // TK + 8 pad: 144B row stride (16B aligned; ldmatrix
                         // 8-row groups conflict-free)
#define ST 3             // cp.async stages (110.6KB smem -> 2 CTA/SM: 221KB<=228KB)

#define A_ELEMS (TM*AST)              // elems per A stage
#define STAGE_ELEMS (2*A_ELEMS)       // A + B
#define DYN_BYTES (ST*STAGE_ELEMS*2)  // 110592 B dynamic smem

// ---------------------------------------------------------------------------
// Scratch (__device__ globals).  A-type row = [hi|lo|hi], B-type = [hi|hi|lo]:
// plain bf16 GEMM over tripled K computes hi*hi + lo*hi + hi*lo.
// ---------------------------------------------------------------------------
__device__ __nv_bfloat16 g_xs[(size_t)MM * K3];
__device__ __nv_bfloat16 g_wq[(size_t)DD * K3];
__device__ __nv_bfloat16 g_wk[(size_t)DD * K3];
__device__ __nv_bfloat16 g_wv[(size_t)DD * K3];
__device__ __nv_bfloat16 g_qs[(size_t)MM * K3];
__device__ __nv_bfloat16 g_ks[(size_t)MM * K3];
__device__ __nv_bfloat16 g_vt[(size_t)BB * DD * S3];
__device__ float         g_sc[(size_t)BB * SS * SS];
__device__ __nv_bfloat16 g_ps[(size_t)BB * SS * S3];

__device__ __forceinline__ void split2(float v, __nv_bfloat16& h, __nv_bfloat16& l) {
    h = __float2bfloat16(v);
    l = __float2bfloat16(v - __bfloat162float(h));
}

// ---------------------------------------------------------------------------
// Split input kernels
// ---------------------------------------------------------------------------
__global__ __launch_bounds__(256) void split_x_kernel(const float* __restrict__ x)
{
    size_t idx = (size_t)blockIdx.x * 256 + threadIdx.x;
    size_t m = idx >> 10, d = idx & (DD - 1);
    __nv_bfloat16 h, l;
    split2(x[idx], h, l);
    __nv_bfloat16* r = g_xs + m * K3;
    r[d] = h; r[DD + d] = l; r[2 * DD + d] = h;            // A-type
}

__global__ __launch_bounds__(256) void split_w_kernel(
    const float* __restrict__ Wq, const float* __restrict__ Wk,
    const float* __restrict__ Wv)
{
    int z = blockIdx.z;
    size_t idx = (size_t)blockIdx.x * 256 + threadIdx.x;
    const float* W = (z == 0) ? Wq : (z == 1) ? Wk : Wv;
    __nv_bfloat16* O = (z == 0) ? g_wq : (z == 1) ? g_wk : g_wv;
    size_t e = idx >> 10, d = idx & (DD - 1);
    __nv_bfloat16 h, l;
    split2(W[idx], h, l);
    __nv_bfloat16* r = O + e * K3;
    r[d] = h; r[DD + d] = h; r[2 * DD + d] = l;            // B-type
}

// ---------------------------------------------------------------------------
// GEMM core: C[128x128] = A[row0..][.] * B[col0..][.]^T, bf16 K-major.
// TK=64 tiles, 3-stage cp.async ring, register-resident ldmatrix fragment
// pipeline carried ACROSS tile boundaries: k0 fragments of tile t+1 are
// loaded (after the single per-tile barrier) while the k3 HMMA burst of
// tile t executes, so the tensor pipe sees back-to-back mma across tiles.
// Requires ntiles >= 3 (all call sites have ntiles >= 6).
// ---------------------------------------------------------------------------
struct KLin {
    __device__ __forceinline__ int operator()(int t) const { return t * TK; }
};
struct KSeg {
    int tps;  // tiles per segment
    __device__ __forceinline__ int operator()(int t) const {
        int s = t / tps; return s * SS + (t - s * tps) * TK;
    }
};

#define LDSM_X4(r0, r1, r2, r3, addr) \
    asm volatile("ldmatrix.sync.aligned.m8n8.x4.shared.b16 {%0,%1,%2,%3}, [%4];" \
                 : "=r"(r0), "=r"(r1), "=r"(r2), "=r"(r3) : "r"(addr))

template <typename KF>
__device__ __forceinline__ void gemm_core(
    const __nv_bfloat16* __restrict__ A, int row0, size_t lda,
    const __nv_bfloat16* __restrict__ B, int col0, size_t ldb,
    int ntiles, KF koff, float acc[4][4][4])
{
    extern __shared__ __align__(16) __nv_bfloat16 smem[];

    const int tid  = threadIdx.x;
    const int lane = tid & 31, warp = tid >> 5;
    const int wm = (warp & 1) << 6;       // 0/64
    const int wn = (warp >> 1) << 5;      // 0/32/64/96
    const int lr  = lane & 7;
    const int seg = lane >> 3;            // 0..3
    const int lrow = tid >> 3;            // loader row base 0..31
    const int lcol = (tid & 7) << 3;      // loader elem col 0..56

    // ldmatrix lane-address bases (bytes) per pipeline stage
    uint32_t aBase[ST], bBase[ST];
#pragma unroll
    for (int s = 0; s < ST; s++) {
        aBase[s] = (uint32_t)__cvta_generic_to_shared(
            smem + s * STAGE_ELEMS + (wm + ((seg & 1) << 3) + lr) * AST + ((seg >> 1) << 3));
        bBase[s] = (uint32_t)__cvta_generic_to_shared(
            smem + s * STAGE_ELEMS + A_ELEMS + (wn + ((seg >> 1) << 3) + lr) * AST + ((seg & 1) << 3));
    }

    auto LDT = [&](int t) {
        const int ko = koff(t);
        __nv_bfloat16* as = smem + (t % ST) * STAGE_ELEMS;
        __nv_bfloat16* bs = as + A_ELEMS;
#pragma unroll
        for (int i = 0; i < 4; i++) {
            const int r = lrow + (i << 5);
            const void* sa = (const void*)(A + (size_t)(row0 + r) * lda + ko + lcol);
            uint32_t da = (uint32_t)__cvta_generic_to_shared(&as[r * AST + lcol]);
            asm volatile("cp.async.cg.shared.global [%0], [%1], 16;" :: "r"(da), "l"(sa));
            const void* sb = (const void*)(B + (size_t)(col0 + r) * ldb + ko + lcol);
            uint32_t db = (uint32_t)__cvta_generic_to_shared(&bs[r * AST + lcol]);
            asm volatile("cp.async.cg.shared.global [%0], [%1], 16;" :: "r"(db), "l"(sb));
        }
        asm volatile("cp.async.commit_group;" ::: "memory");
    };

    // Prologue: fill all 3 stages, arm k0 fragments of tile 0.
    LDT(0); LDT(1); LDT(2);
    asm volatile("cp.async.wait_group 2;" ::: "memory");
    __syncthreads();

    uint32_t af[2][4][4], bf[2][2][4];
#pragma unroll
    for (int mi = 0; mi < 4; mi++)
        LDSM_X4(af[0][mi][0], af[0][mi][1], af[0][mi][2], af[0][mi][3],
                aBase[0] + mi * (16 * AST * 2));
#pragma unroll
    for (int n2 = 0; n2 < 2; n2++)
        LDSM_X4(bf[0][n2][0], bf[0][n2][1], bf[0][n2][2], bf[0][n2][3],
                bBase[0] + n2 * (16 * AST * 2));

    for (int t = 0; t < ntiles; t++) {
        const int st = t % ST;
        const uint32_t ab = aBase[st], bb = bBase[st];

        // k-steps 0..2: prefetch next k-step fragments, mma current
#pragma unroll
        for (int kk = 0; kk < 3; kk++) {
            const int cur = kk & 1, nxt = cur ^ 1;
            const uint32_t ak = ab + (kk + 1) * 32;
            const uint32_t bk = bb + (kk + 1) * 32;
#pragma unroll
            for (int mi = 0; mi < 4; mi++)
                LDSM_X4(af[nxt][mi][0], af[nxt][mi][1], af[nxt][mi][2], af[nxt][mi][3],
                        ak + mi * (16 * AST * 2));
#pragma unroll
            for (int n2 = 0; n2 < 2; n2++)
                LDSM_X4(bf[nxt][n2][0], bf[nxt][n2][1], bf[nxt][n2][2], bf[nxt][n2][3],
                        bk + n2 * (16 * AST * 2));
#pragma unroll
            for (int mi = 0; mi < 4; mi++)
#pragma unroll
                for (int ni = 0; ni < 4; ni++) {
                    float* c = acc[mi][ni];
                    const uint32_t b0 = bf[cur][ni >> 1][(ni & 1) << 1];
                    const uint32_t b1 = bf[cur][ni >> 1][((ni & 1) << 1) + 1];
                    asm volatile(
                        "mma.sync.aligned.m16n8k16.row.col.f32.bf16.bf16.f32 "
                        "{%0,%1,%2,%3}, {%4,%5,%6,%7}, {%8,%9}, {%0,%1,%2,%3};\n"
                        : "+f"(c[0]), "+f"(c[1]), "+f"(c[2]), "+f"(c[3])
                        : "r"(af[cur][mi][0]), "r"(af[cur][mi][1]),
                          "r"(af[cur][mi][2]), "r"(af[cur][mi][3]),
                          "r"(b0), "r"(b1));
                }
        }

        // k-step 3: publish stage t+1, preload its k0 fragments, then mma k3.
        if (t + 1 < ntiles) {
            if (t + 3 <= ntiles) { asm volatile("cp.async.wait_group 1;" ::: "memory"); }
            else                 { asm volatile("cp.async.wait_group 0;" ::: "memory"); }
            __syncthreads();                       // publish stage t+1; drain stage t reads
            const int sn = (t + 1) % ST;
#pragma unroll
            for (int mi = 0; mi < 4; mi++)
                LDSM_X4(af[0][mi][0], af[0][mi][1], af[0][mi][2], af[0][mi][3],
                        aBase[sn] + mi * (16 * AST * 2));
#pragma unroll
            for (int n2 = 0; n2 < 2; n2++)
                LDSM_X4(bf[0][n2][0], bf[0][n2][1], bf[0][n2][2], bf[0][n2][3],
                        bBase[sn] + n2 * (16 * AST * 2));
        }
#pragma unroll
        for (int mi = 0; mi < 4; mi++)
#pragma unroll
            for (int ni = 0; ni < 4; ni++) {
                float* c = acc[mi][ni];
                const uint32_t b0 = bf[1][ni >> 1][(ni & 1) << 1];
                const uint32_t b1 = bf[1][ni >> 1][((ni & 1) << 1) + 1];
                asm volatile(
                    "mma.sync.aligned.m16n8k16.row.col.f32.bf16.bf16.f32 "
                    "{%0,%1,%2,%3}, {%4,%5,%6,%7}, {%8,%9}, {%0,%1,%2,%3};\n"
                    : "+f"(c[0]), "+f"(c[1]), "+f"(c[2]), "+f"(c[3])
                    : "r"(af[1][mi][0]), "r"(af[1][mi][1]),
                      "r"(af[1][mi][2]), "r"(af[1][mi][3]),
                      "r"(b0), "r"(b1));
            }

        if (t + 3 < ntiles) LDT(t + 3);            // refill stage just drained
    }
    __syncthreads();
}

// ---------------------------------------------------------------------------
// Kernel: QKV projections (z = 0/1/2 -> Q/K/V), epilogue writes bf16 splits.
// ---------------------------------------------------------------------------
__global__ __launch_bounds__(256, 2) void proj_kernel(
    const float* __restrict__ bq, const float* __restrict__ bk,
    const float* __restrict__ bv)
{
    const int z = blockIdx.z;
    const __nv_bfloat16* W = (z == 0) ? g_wq : (z == 1) ? g_wk : g_wv;
    const float* bias      = (z == 0) ? bq   : (z == 1) ? bk   : bv;
    const int row0 = blockIdx.y * TM, col0 = blockIdx.x * TN;

    float acc[4][4][4];
#pragma unroll
    for (int i = 0; i < 4; i++)
#pragma unroll
        for (int j = 0; j < 4; j++)
#pragma unroll
            for (int q = 0; q < 4; q++) acc[i][j][q] = 0.f;

    gemm_core(g_xs, row0, K3, W, col0, K3, K3 / TK, KLin{}, acc);

    const int lane = threadIdx.x & 31, warp = threadIdx.x >> 5;
    const int wm = (warp & 1) << 6, wn = (warp >> 1) << 5;
    const int g = lane >> 2, tig = lane & 3;

#pragma unroll
    for (int mi = 0; mi < 4; mi++)
#pragma unroll
        for (int ni = 0; ni < 4; ni++) {
            const int n = col0 + wn + (ni << 3) + (tig << 1);
            const float b0 = bias[n], b1 = bias[n + 1];
#pragma unroll
            for (int rr = 0; rr < 2; rr++) {
                const int m = row0 + wm + (mi << 4) + g + rr * 8;
                float v0 = acc[mi][ni][rr * 2 + 0] + b0;
                float v1 = acc[mi][ni][rr * 2 + 1] + b1;
                __nv_bfloat16 h0, l0, h1, l1;
                split2(v0, h0, l0); split2(v1, h1, l1);
                if (z == 0) {          // Q: A-type [hi|lo|hi]
                    __nv_bfloat16* r = g_qs + (size_t)m * K3 + n;
                    __nv_bfloat162 th; th.x = h0; th.y = h1;
                    __nv_bfloat162 tl; tl.x = l0; tl.y = l1;
                    *(__nv_bfloat162*)(r)          = th;
                    *(__nv_bfloat162*)(r + DD)     = tl;
                    *(__nv_bfloat162*)(r + 2 * DD) = th;
                } else if (z == 1) {   // K: B-type [hi|hi|lo]
                    __nv_bfloat16* r = g_ks + (size_t)m * K3 + n;
                    __nv_bfloat162 th; th.x = h0; th.y = h1;
                    __nv_bfloat162 tl; tl.x = l0; tl.y = l1;
                    *(__nv_bfloat162*)(r)          = th;
                    *(__nv_bfloat162*)(r + DD)     = th;
                    *(__nv_bfloat162*)(r + 2 * DD) = tl;
                } else {               // V: transposed into g_vt[b][d][3S], B-type
                    const int b = m >> 11, s = m & (SS - 1);
                    __nv_bfloat16* r0 = g_vt + ((size_t)b * DD + n) * S3 + s;
                    r0[0] = h0; r0[SS] = h0; r0[2 * SS] = l0;
                    __nv_bfloat16* r1 = g_vt + ((size_t)b * DD + n + 1) * S3 + s;
                    r1[0] = h1; r1[SS] = h1; r1[2 * SS] = l1;
                }
            }
        }
}

// ---------------------------------------------------------------------------
// Kernel: scores = Q K^T / sqrt(D); causal upper blocks skipped entirely.
// ---------------------------------------------------------------------------
__global__ __launch_bounds__(256, 2) void scores_kernel()
{
    const int bx = blockIdx.x, by = blockIdx.y, b = blockIdx.z;
    if (bx > by) return;
    const __nv_bfloat16* A  = g_qs + (size_t)b * SS * K3;
    const __nv_bfloat16* Bp = g_ks + (size_t)b * SS * K3;
    const int row0 = by * TM, col0 = bx * TN;

    float acc[4][4][4];
#pragma unroll
    for (int i = 0; i < 4; i++)
#pragma unroll
        for (int j = 0; j < 4; j++)
#pragma unroll
            for (int q = 0; q < 4; q++) acc[i][j][q] = 0.f;

    gemm_core(A, row0, K3, Bp, col0, K3, K3 / TK, KLin{}, acc);

    float* C = g_sc + (size_t)b * SS * SS;
    const int lane = threadIdx.x & 31, warp = threadIdx.x >> 5;
    const int wm = (warp & 1) << 6, wn = (warp >> 1) << 5;
    const int g = lane >> 2, tig = lane & 3;

#pragma unroll
    for (int mi = 0; mi < 4; mi++)
#pragma unroll
        for (int ni = 0; ni < 4; ni++) {
            const int n = col0 + wn + (ni << 3) + (tig << 1);
#pragma unroll
            for (int rr = 0; rr < 2; rr++) {
                const int m = row0 + wm + (mi << 4) + g + rr * 8;
                float2 v;
                v.x = acc[mi][ni][rr * 2 + 0] * 0.03125f;
                v.y = acc[mi][ni][rr * 2 + 1] * 0.03125f;
                *(float2*)(C + (size_t)m * SS + n) = v;
            }
        }
}

// ---------------------------------------------------------------------------
// Kernel: causal row softmax; writes split weights (A-type) with zero fill.
// ---------------------------------------------------------------------------
__global__ __launch_bounds__(256) void softmax_kernel()
{
    const int row = blockIdx.x;
    const int b = row >> 11;
    const int i = row & (SS - 1);
    const float* p = g_sc + (size_t)b * SS * SS + (size_t)i * SS;
    __nv_bfloat16* o = g_ps + (size_t)b * SS * S3 + (size_t)i * S3;
    const int len = i + 1;
    const int tid = threadIdx.x;
    const int lane = tid & 31, wid = tid >> 5;
    __shared__ float red[8];

    float m = __int_as_float(0xff800000);
    float xv[8];
#pragma unroll
    for (int jj = 0; jj < 8; jj++) {
        int j = tid + jj * 256;
        xv[jj] = (j < len) ? p[j] : __int_as_float(0xff800000);
        m = fmaxf(m, xv[jj]);
    }
#pragma unroll
    for (int off = 16; off; off >>= 1) m = fmaxf(m, __shfl_xor_sync(0xffffffffu, m, off));
    if (lane == 0) red[wid] = m;
    __syncthreads();
    if (tid == 0) {
        float mm = red[0];
#pragma unroll
        for (int w = 1; w < 8; w++) mm = fmaxf(mm, red[w]);
        red[0] = mm;
    }
    __syncthreads();
    m = red[0];
    __syncthreads();

    float s = 0.f;
    float ev[8];
#pragma unroll
    for (int jj = 0; jj < 8; jj++) {
        int j = tid + jj * 256;
        ev[jj] = (j < len) ? __expf(xv[jj] - m) : 0.f;
        s += ev[jj];
    }
#pragma unroll
    for (int off = 16; off; off >>= 1) s += __shfl_xor_sync(0xffffffffu, s, off);
    if (lane == 0) red[wid] = s;
    __syncthreads();
    if (tid == 0) {
        float ss = 0.f;
#pragma unroll
        for (int w = 0; w < 8; w++) ss += red[w];
        red[0] = ss;
    }
    __syncthreads();
    const float inv = 1.f / red[0];

#pragma unroll
    for (int jj = 0; jj < 8; jj++) {
        int j = tid + jj * 256;
        float w = ev[jj] * inv;
        __nv_bfloat16 h, l;
        split2(w, h, l);
        o[j] = h; o[SS + j] = l; o[2 * SS + j] = h;        // A-type
    }
}

// ---------------------------------------------------------------------------
// Kernel: out = P V ; K runs 3 causal-capped segments (hi, lo, hi parts).
// ---------------------------------------------------------------------------
__global__ __launch_bounds__(256, 2) void pv_kernel(float* __restrict__ out)
{
    const int bx = blockIdx.x, by = blockIdx.y, b = blockIdx.z;
    const __nv_bfloat16* A  = g_ps + (size_t)b * SS * S3;
    const __nv_bfloat16* Bp = g_vt + (size_t)b * DD * S3;
    const int row0 = by * TM, col0 = bx * TN;
    const int tps = (row0 + TM) / TK;      // causal cap per segment

    float acc[4][4][4];
#pragma unroll
    for (int i = 0; i < 4; i++)
#pragma unroll
        for (int j = 0; j < 4; j++)
#pragma unroll
            for (int q = 0; q < 4; q++) acc[i][j][q] = 0.f;

    gemm_core(A, row0, S3, Bp, col0, S3, 3 * tps, KSeg{tps}, acc);

    float* C = out + (size_t)b * SS * DD;
    const int lane = threadIdx.x & 31, warp = threadIdx.x >> 5;
    const int wm = (warp & 1) << 6, wn = (warp >> 1) << 5;
    const int g = lane >> 2, tig = lane & 3;

#pragma unroll
    for (int mi = 0; mi < 4; mi++)
#pragma unroll
        for (int ni = 0; ni < 4; ni++) {
            const int n = col0 + wn + (ni << 3) + (tig << 1);
#pragma unroll
            for (int rr = 0; rr < 2; rr++) {
                const int m = row0 + wm + (mi << 4) + g + rr * 8;
                float2 v;
                v.x = acc[mi][ni][rr * 2 + 0];
                v.y = acc[mi][ni][rr * 2 + 1];
                *(float2*)(C + (size_t)m * DD + n) = v;
            }
        }
}

// ---------------------------------------------------------------------------
extern "C" void kernel_launch(void* const* d_in, const int* in_sizes, int n_in,
                              void* d_out, int out_size)
{
    const float* x  = (const float*)d_in[0];
    const float* Wq = (const float*)d_in[1];
    const float* bq = (const float*)d_in[2];
    const float* Wk = (const float*)d_in[3];
    const float* bk = (const float*)d_in[4];
    const float* Wv = (const float*)d_in[5];
    const float* bv = (const float*)d_in[6];
    float* out = (float*)d_out;

    cudaFuncSetAttribute(proj_kernel,   cudaFuncAttributeMaxDynamicSharedMemorySize, DYN_BYTES);
    cudaFuncSetAttribute(scores_kernel, cudaFuncAttributeMaxDynamicSharedMemorySize, DYN_BYTES);
    cudaFuncSetAttribute(pv_kernel,     cudaFuncAttributeMaxDynamicSharedMemorySize, DYN_BYTES);

    split_x_kernel<<<(MM * DD) / 256, 256>>>(x);
    split_w_kernel<<<dim3((DD * DD) / 256, 1, 3), 256>>>(Wq, Wk, Wv);
    proj_kernel<<<dim3(DD / TN, MM / TM, 3), 256, DYN_BYTES>>>(bq, bk, bv);
    scores_kernel<<<dim3(SS / TN, SS / TM, BB), 256, DYN_BYTES>>>();
    softmax_kernel<<<BB * SS, 256>>>();
    pv_kernel<<<dim3(DD / TN, SS / TM, BB), 256, DYN_BYTES>>>(out);
}